// round 3
// baseline (speedup 1.0000x reference)
#include <cuda_runtime.h>
#include <cuda_bf16.h>
#include <cstddef>
#include <cstdint>

// ---------------- problem constants ----------------
// S=32, T=64, B=64, E=H=G=128, C=5
#define M1 131072      // S*T*B token rows
#define M2 2048        // S*B sentence rows

// ---------------- scratch ----------------
__device__ float g_xg  [100663296];  // [M1][768]
__device__ float g_out1[33554432];   // [M1][256]
__device__ float g_logit[131072];
__device__ float g_sent[524288];     // [M2][256]
__device__ float g_xg2 [1572864];    // [M2][768]
__device__ float g_out2[524288];     // [M2][256]
__device__ float g_a2  [2048];

__device__ __forceinline__ float sigf(float x) { return 1.f / (1.f + __expf(-x)); }
__device__ __forceinline__ float tanh_clamped(float x) {
    float a = fminf(fmaxf(x, -15.f), 15.f);
    float e = __expf(-2.f * a);
    return (1.f - e) / (1.f + e);
}

// =====================================================================
// GEMM: C[m][n0..] = A'[m] . W[n] + bias[n], A' rows gathered via tokens
// BM=128, BN=64, BK=16, 256 threads, 8m x 4n microtile.
// =====================================================================
template<int KDIM>
__global__ void __launch_bounds__(256) gemm_xg(
    const float* __restrict__ A, const int* __restrict__ tokens,
    const float* __restrict__ W, const float* __restrict__ bias,
    float* __restrict__ C, int Ntot)
{
    __shared__ float As[16][128];
    __shared__ float Ws[16][64];
    const int tid = threadIdx.x;
    const int m0 = blockIdx.y * 128, n0 = blockIdx.x * 64;
    const int tx = tid & 15, ty = tid >> 4;

    const int r  = tid >> 2;          // 0..63
    const int kc = (tid & 3) << 2;    // 0,4,8,12
    const float* arow0;
    const float* arow1;
    if (tokens) {
        arow0 = A + (size_t)tokens[m0 + r]      * KDIM;
        arow1 = A + (size_t)tokens[m0 + r + 64] * KDIM;
    } else {
        arow0 = A + (size_t)(m0 + r)      * KDIM;
        arow1 = A + (size_t)(m0 + r + 64) * KDIM;
    }
    const float* wrow = W + (size_t)(n0 + r) * KDIM;

    float acc[8][4];
#pragma unroll
    for (int i = 0; i < 8; i++)
#pragma unroll
        for (int j = 0; j < 4; j++) acc[i][j] = 0.f;

    for (int k0 = 0; k0 < KDIM; k0 += 16) {
        float4 a0 = *(const float4*)(arow0 + k0 + kc);
        float4 a1 = *(const float4*)(arow1 + k0 + kc);
        float4 w0 = *(const float4*)(wrow  + k0 + kc);
        __syncthreads();
        As[kc + 0][r] = a0.x; As[kc + 1][r] = a0.y; As[kc + 2][r] = a0.z; As[kc + 3][r] = a0.w;
        As[kc + 0][r + 64] = a1.x; As[kc + 1][r + 64] = a1.y; As[kc + 2][r + 64] = a1.z; As[kc + 3][r + 64] = a1.w;
        Ws[kc + 0][r] = w0.x; Ws[kc + 1][r] = w0.y; Ws[kc + 2][r] = w0.z; Ws[kc + 3][r] = w0.w;
        __syncthreads();
#pragma unroll
        for (int k = 0; k < 16; k++) {
            float4 av0 = *(const float4*)&As[k][ty * 8];
            float4 av1 = *(const float4*)&As[k][ty * 8 + 4];
            float4 wv  = *(const float4*)&Ws[k][tx * 4];
            float am[8] = {av0.x, av0.y, av0.z, av0.w, av1.x, av1.y, av1.z, av1.w};
            float wn[4] = {wv.x, wv.y, wv.z, wv.w};
#pragma unroll
            for (int mm = 0; mm < 8; mm++)
#pragma unroll
                for (int nn = 0; nn < 4; nn++) acc[mm][nn] += am[mm] * wn[nn];
        }
    }
    float4 bv = *(const float4*)(bias + n0 + tx * 4);
    float bn[4] = {bv.x, bv.y, bv.z, bv.w};
#pragma unroll
    for (int mm = 0; mm < 8; mm++) {
        int m = m0 + ty * 8 + mm;
        float4 o = make_float4(acc[mm][0] + bn[0], acc[mm][1] + bn[1],
                               acc[mm][2] + bn[2], acc[mm][3] + bn[3]);
        *(float4*)(C + (size_t)m * Ntot + n0 + tx * 4) = o;
    }
}

// =====================================================================
// GRU recurrence. One CTA handles (chain, dir, 32-batch tile), 256 thr.
// Whh^T (Wt[k][g], 192KB) + swizzled h (ht[j][b], 4KB) in dynamic smem.
// Thread tile: 4b x 4j x 3gates. grid = (B/32, 2, nchains).
// =====================================================================
__global__ void __launch_bounds__(256) gru_rec(
    const float* __restrict__ xg, float* __restrict__ out,
    const float* __restrict__ Whh, const float* __restrict__ bhh,
    int nsteps, size_t chain_xg, size_t chain_out)
{
    extern __shared__ float sm[];
    float* Wt = sm;               // [128][384]
    float* ht = sm + 128 * 384;   // [128][32] swizzled
    const int tid = threadIdx.x, lane = tid & 31, warp = tid >> 5;
    const int dir = blockIdx.y, chain = blockIdx.z;
    const int bCTA = blockIdx.x * 32;
    const int bl = warp * 4;          // local batch base (0..28)
    const int j0 = lane * 4;          // hidden base (0..124)
    const int swz_self = (lane & 7) << 2;

    const float* wsrc = Whh + (size_t)dir * 384 * 128;
    for (int idx = tid; idx < 384 * 32; idx += 256) {
        int g = idx >> 5, kk = (idx & 31) << 2;
        float4 v = *(const float4*)(wsrc + g * 128 + kk);
        Wt[(kk + 0) * 384 + g] = v.x; Wt[(kk + 1) * 384 + g] = v.y;
        Wt[(kk + 2) * 384 + g] = v.z; Wt[(kk + 3) * 384 + g] = v.w;
    }
    for (int idx = tid; idx < 128 * 32; idx += 256) ht[idx] = 0.f;

    float bh[3][4];
#pragma unroll
    for (int g = 0; g < 3; g++) {
        float4 v = *(const float4*)(bhh + dir * 384 + g * 128 + j0);
        bh[g][0] = v.x; bh[g][1] = v.y; bh[g][2] = v.z; bh[g][3] = v.w;
    }
    const float* xbase = xg + chain * chain_xg + dir * 384;
    float* obase = out + chain * chain_out + dir * 128;
    __syncthreads();

    for (int stp = 0; stp < nsteps; stp++) {
        const int t = dir ? (nsteps - 1 - stp) : stp;
        // prefetch this step's input gates (consumed after k-loop)
        float xv[3][4][4];
#pragma unroll
        for (int bb = 0; bb < 4; bb++) {
            const float* row = xbase + ((size_t)t * 64 + bCTA + bl + bb) * 768;
#pragma unroll
            for (int g = 0; g < 3; g++) {
                float4 v = *(const float4*)(row + g * 128 + j0);
                xv[g][bb][0] = v.x; xv[g][bb][1] = v.y; xv[g][bb][2] = v.z; xv[g][bb][3] = v.w;
            }
        }
        float acc[3][4][4];
#pragma unroll
        for (int g = 0; g < 3; g++)
#pragma unroll
            for (int bb = 0; bb < 4; bb++)
#pragma unroll
                for (int jj = 0; jj < 4; jj++) acc[g][bb][jj] = bh[g][jj];

#pragma unroll 4
        for (int k = 0; k < 128; k++) {
            int sw = ((k >> 2) & 7) << 2;
            float4 hv = *(const float4*)&ht[k * 32 + (bl ^ sw)];
            const float* wk = Wt + k * 384 + j0;
            float4 wr = *(const float4*)(wk);
            float4 wz = *(const float4*)(wk + 128);
            float4 wn = *(const float4*)(wk + 256);
            float hb[4] = {hv.x, hv.y, hv.z, hv.w};
            float r4[4] = {wr.x, wr.y, wr.z, wr.w};
            float z4[4] = {wz.x, wz.y, wz.z, wz.w};
            float n4[4] = {wn.x, wn.y, wn.z, wn.w};
#pragma unroll
            for (int bb = 0; bb < 4; bb++)
#pragma unroll
                for (int jj = 0; jj < 4; jj++) {
                    acc[0][bb][jj] += hb[bb] * r4[jj];
                    acc[1][bb][jj] += hb[bb] * z4[jj];
                    acc[2][bb][jj] += hb[bb] * n4[jj];
                }
        }
        float hold[4][4];
#pragma unroll
        for (int bb = 0; bb < 4; bb++)
#pragma unroll
            for (int jj = 0; jj < 4; jj++)
                hold[bb][jj] = ht[(j0 + jj) * 32 + ((bl + bb) ^ swz_self)];
        __syncthreads();   // all reads of old h done

#pragma unroll
        for (int bb = 0; bb < 4; bb++) {
            float4 o;
            float* op = (float*)&o;
#pragma unroll
            for (int jj = 0; jj < 4; jj++) {
                float r = sigf(xv[0][bb][jj] + acc[0][bb][jj]);
                float z = sigf(xv[1][bb][jj] + acc[1][bb][jj]);
                float n = tanh_clamped(xv[2][bb][jj] + r * acc[2][bb][jj]);
                float h = (1.f - z) * n + z * hold[bb][jj];
                ht[(j0 + jj) * 32 + ((bl + bb) ^ swz_self)] = h;
                op[jj] = h;
            }
            *(float4*)(obase + ((size_t)t * 64 + bCTA + bl + bb) * 256 + j0) = o;
        }
        __syncthreads();   // new h visible
    }
}

// =====================================================================
// logit[m] = sum_n tanh( (A[m] . W[:,n]) + bias[n] ) * proj[n]
// A [M][256], W [256][256] row-major (h-major). BM=32, BN=256 full.
// =====================================================================
__global__ void __launch_bounds__(256) att_logits(
    const float* __restrict__ A, const float* __restrict__ W,
    const float* __restrict__ bias, const float* __restrict__ proj,
    float* __restrict__ logit)
{
    __shared__ float As[16][32];
    __shared__ float Ws[16][256];
    const int tid = threadIdx.x;
    const int tx = tid & 31, ty = tid >> 5;      // tx=lane (n), ty=warp (m)
    const int m0 = blockIdx.x * 32;

    const int arow = tid & 31, akc = (tid >> 5) << 1;     // load map for A
    const int wkr = tid >> 6, wcol = (tid & 63) << 2;     // load map for W

    float acc[4][8];
#pragma unroll
    for (int i = 0; i < 4; i++)
#pragma unroll
        for (int j = 0; j < 8; j++) acc[i][j] = 0.f;

    for (int k0 = 0; k0 < 256; k0 += 16) {
        float2 av = *(const float2*)(A + (size_t)(m0 + arow) * 256 + k0 + akc);
        float4 wv[4];
#pragma unroll
        for (int i = 0; i < 4; i++)
            wv[i] = *(const float4*)(W + (size_t)(k0 + wkr + i * 4) * 256 + wcol);
        __syncthreads();
        As[akc][arow] = av.x; As[akc + 1][arow] = av.y;
#pragma unroll
        for (int i = 0; i < 4; i++)
            *(float4*)&Ws[wkr + i * 4][wcol] = wv[i];
        __syncthreads();
#pragma unroll
        for (int k = 0; k < 16; k++) {
            float4 a4 = *(const float4*)&As[k][ty * 4];
            float4 w0 = *(const float4*)&Ws[k][tx * 8];
            float4 w1 = *(const float4*)&Ws[k][tx * 8 + 4];
            float am[4] = {a4.x, a4.y, a4.z, a4.w};
            float wn[8] = {w0.x, w0.y, w0.z, w0.w, w1.x, w1.y, w1.z, w1.w};
#pragma unroll
            for (int mm = 0; mm < 4; mm++)
#pragma unroll
                for (int nn = 0; nn < 8; nn++) acc[mm][nn] += am[mm] * wn[nn];
        }
    }
    float4 b0 = *(const float4*)(bias + tx * 8);
    float4 b1 = *(const float4*)(bias + tx * 8 + 4);
    float4 p0 = *(const float4*)(proj + tx * 8);
    float4 p1 = *(const float4*)(proj + tx * 8 + 4);
    float bn[8] = {b0.x, b0.y, b0.z, b0.w, b1.x, b1.y, b1.z, b1.w};
    float pn[8] = {p0.x, p0.y, p0.z, p0.w, p1.x, p1.y, p1.z, p1.w};
#pragma unroll
    for (int mm = 0; mm < 4; mm++) {
        float part = 0.f;
#pragma unroll
        for (int nn = 0; nn < 8; nn++)
            part += tanh_clamped(acc[mm][nn] + bn[nn]) * pn[nn];
#pragma unroll
        for (int off = 16; off > 0; off >>= 1)
            part += __shfl_xor_sync(0xffffffffu, part, off);
        if (tx == 0) logit[m0 + ty * 4 + mm] = part;
    }
}

// ===================== softmax over T + weighted sum =================
__global__ void __launch_bounds__(256) softk(
    const float* __restrict__ logit, const float* __restrict__ out1,
    float* __restrict__ sent)
{
    const int s = blockIdx.x, b = blockIdx.y, tid = threadIdx.x;
    __shared__ float w[64];
    if (tid < 64) w[tid] = logit[(s * 64 + tid) * 64 + b];
    __syncthreads();
    if (tid < 32) {
        float a0 = w[tid], a1 = w[tid + 32];
        float mx = fmaxf(a0, a1);
#pragma unroll
        for (int off = 16; off > 0; off >>= 1)
            mx = fmaxf(mx, __shfl_xor_sync(0xffffffffu, mx, off));
        float e0 = __expf(a0 - mx), e1 = __expf(a1 - mx);
        float sum = e0 + e1;
#pragma unroll
        for (int off = 16; off > 0; off >>= 1)
            sum += __shfl_xor_sync(0xffffffffu, sum, off);
        float inv = 1.f / sum;
        w[tid] = e0 * inv; w[tid + 32] = e1 * inv;
    }
    __syncthreads();
    float acc = 0.f;
    const float* base = out1 + ((size_t)s * 64 * 64 + b) * 256 + tid;
#pragma unroll 8
    for (int t = 0; t < 64; t++)
        acc += w[t] * base[(size_t)t * 64 * 256];
    sent[(size_t)(s * 64 + b) * 256 + tid] = acc;
}

// ===================== final: doc vec + linear =======================
__global__ void __launch_bounds__(256) finalk(
    const float* __restrict__ out2, const float* __restrict__ a2,
    const float* __restrict__ Wf, const float* __restrict__ bf,
    float* __restrict__ out)
{
    const int b = blockIdx.x, tid = threadIdx.x;
    __shared__ float doc[256];
    float acc = 0.f;
#pragma unroll 8
    for (int s = 0; s < 32; s++)
        acc += a2[s * 64 + b] * out2[(size_t)(s * 64 + b) * 256 + tid];
    doc[tid] = acc;
    __syncthreads();
    if (tid < 5) {
        float r = bf[tid];
        for (int h = 0; h < 256; h++) r += doc[h] * Wf[tid * 256 + h];
        out[b * 5 + tid] = r;
    }
}

// =====================================================================
extern "C" void kernel_launch(void* const* d_in, const int* in_sizes, int n_in,
                              void* d_out, int out_size)
{
    (void)in_sizes; (void)n_in; (void)out_size;
    const int*   tokens = (const int*)  d_in[0];
    const float* embed  = (const float*)d_in[1];
    const float* Wih_a  = (const float*)d_in[2];
    const float* Whh_a  = (const float*)d_in[3];
    const float* bih_a  = (const float*)d_in[4];
    const float* bhh_a  = (const float*)d_in[5];
    const float* WW_a   = (const float*)d_in[6];
    const float* b_a    = (const float*)d_in[7];
    const float* proj_a = (const float*)d_in[8];
    const float* Wih_b  = (const float*)d_in[9];
    const float* Whh_b  = (const float*)d_in[10];
    const float* bih_b  = (const float*)d_in[11];
    const float* bhh_b  = (const float*)d_in[12];
    const float* WW_b   = (const float*)d_in[13];
    const float* b_b    = (const float*)d_in[14];
    const float* proj_b = (const float*)d_in[15];
    const float* Wf     = (const float*)d_in[16];
    const float* bf     = (const float*)d_in[17];
    float* out = (float*)d_out;

    float *xg, *out1, *logit, *sent, *xg2, *out2, *a2;
    cudaGetSymbolAddress((void**)&xg,    g_xg);
    cudaGetSymbolAddress((void**)&out1,  g_out1);
    cudaGetSymbolAddress((void**)&logit, g_logit);
    cudaGetSymbolAddress((void**)&sent,  g_sent);
    cudaGetSymbolAddress((void**)&xg2,   g_xg2);
    cudaGetSymbolAddress((void**)&out2,  g_out2);
    cudaGetSymbolAddress((void**)&a2,    g_a2);

    const int rec_smem = (128 * 384 + 128 * 32) * (int)sizeof(float);  // 212992
    cudaFuncSetAttribute(gru_rec, cudaFuncAttributeMaxDynamicSharedMemorySize, rec_smem);

    // 1) intra input gates: [131072,768] = gather(emb) @ Wih_intra^T + bih
    gemm_xg<128><<<dim3(12, 1024), 256>>>(embed, tokens, Wih_a, bih_a, xg, 768);
    // 2) intra biGRU: 32 chains x 2 dirs x 2 batch tiles
    gru_rec<<<dim3(2, 2, 32), 256, rec_smem>>>(
        xg, out1, Whh_a, bhh_a, 64, (size_t)64 * 64 * 768, (size_t)64 * 64 * 256);
    // 3) token attention logits
    att_logits<<<4096, 256>>>(out1, WW_a, b_a, proj_a, logit);
    // 4) softmax over tokens + weighted sum -> sentence vectors
    softk<<<dim3(32, 64), 256>>>(logit, out1, sent);
    // 5) inter input gates: [2048,768] = sent @ Wih_inter^T + bih
    gemm_xg<256><<<dim3(12, 16), 256>>>(sent, nullptr, Wih_b, bih_b, xg2, 768);
    // 6) inter biGRU: 1 chain x 2 dirs x 2 batch tiles
    gru_rec<<<dim3(2, 2, 1), 256, rec_smem>>>(
        xg2, out2, Whh_b, bhh_b, 32, 0, 0);
    // 7) sentence attention scores (no softmax)
    att_logits<<<64, 256>>>(out2, WW_b, b_b, proj_b, a2);
    // 8) doc vector + final linear
    finalk<<<64, 256>>>(out2, a2, Wf, bf, out);
}

// round 4
// speedup vs baseline: 1.2745x; 1.2745x over previous
#include <cuda_runtime.h>
#include <cuda_bf16.h>
#include <cstddef>
#include <cstdint>

// S=32, T=64, B=64, E=H=G=128, C=5
#define M1 131072
#define M2 2048

__device__ float g_xg  [100663296];  // [M1][768]
__device__ float g_out1[33554432];   // [M1][256]
__device__ float g_logit[131072];
__device__ float g_sent[524288];     // [M2][256]
__device__ float g_xg2 [1572864];    // [M2][768]
__device__ float g_out2[524288];     // [M2][256]
__device__ float g_a2  [2048];

__device__ __forceinline__ float sigf(float x) { return 1.f / (1.f + __expf(-x)); }
__device__ __forceinline__ float tanh_clamped(float x) {
    float a = fminf(fmaxf(x, -15.f), 15.f);
    float e = __expf(-2.f * a);
    return (1.f - e) / (1.f + e);
}
__device__ __forceinline__ uint32_t f2tf(float x) {
    uint32_t r; asm("cvt.rna.tf32.f32 %0, %1;" : "=r"(r) : "f"(x)); return r;
}
__device__ __forceinline__ void mma_tf32(float* d, const uint32_t* a, const uint32_t* b) {
    asm volatile(
        "mma.sync.aligned.m16n8k8.row.col.f32.tf32.tf32.f32 "
        "{%0,%1,%2,%3}, {%4,%5,%6,%7}, {%8,%9}, {%0,%1,%2,%3};\n"
        : "+f"(d[0]), "+f"(d[1]), "+f"(d[2]), "+f"(d[3])
        : "r"(a[0]), "r"(a[1]), "r"(a[2]), "r"(a[3]), "r"(b[0]), "r"(b[1]));
}

// =====================================================================
// TC GEMM: C[m][n] = A'[m] . W[n] + bias[n]; A' gathered if GATHER.
// A [M][K] row-major (K-contig), W [N][K] row-major (K-contig).
// Tile 128x128, K-chunks of 128. 256 thr, warps 2m x 4n, warp 64x32.
// =====================================================================
template<bool GATHER>
__global__ void __launch_bounds__(256) gemm_tc(
    const float* __restrict__ A, const int* __restrict__ tokens,
    const float* __restrict__ W, const float* __restrict__ bias,
    float* __restrict__ C, int Ntot, int K)
{
    extern __shared__ uint32_t smg[];
    uint32_t* As = smg;                 // [128][132]
    uint32_t* Ws = smg + 128 * 132;     // [128][132]
    const int tid = threadIdx.x, lane = tid & 31, w = tid >> 5;
    const int g = lane >> 2, tg = lane & 3;
    const int m0 = blockIdx.y * 128, n0 = blockIdx.x * 128;
    const int mwo = (w >> 2) * 64, nwo = (w & 3) * 32;

    const int lr = tid >> 1, lh = (tid & 1) * 64;   // load row, col half
    size_t arow;
    if (GATHER) arow = (size_t)tokens[m0 + lr] * K;
    else        arow = (size_t)(m0 + lr) * K;
    const size_t wrow = (size_t)(n0 + lr) * K;

    float acc[4][4][4];
#pragma unroll
    for (int a = 0; a < 4; a++)
#pragma unroll
        for (int b = 0; b < 4; b++)
#pragma unroll
            for (int c = 0; c < 4; c++) acc[a][b][c] = 0.f;

    for (int kc = 0; kc < K; kc += 128) {
#pragma unroll
        for (int i = 0; i < 16; i++) {
            int col = lh + i * 4;
            float4 av = *(const float4*)(A + arow + kc + col);
            float4 wv = *(const float4*)(W + wrow + kc + col);
            uint32_t* ad = As + lr * 132 + col;
            uint32_t* wd = Ws + lr * 132 + col;
            ad[0] = f2tf(av.x); ad[1] = f2tf(av.y); ad[2] = f2tf(av.z); ad[3] = f2tf(av.w);
            wd[0] = f2tf(wv.x); wd[1] = f2tf(wv.y); wd[2] = f2tf(wv.z); wd[3] = f2tf(wv.w);
        }
        __syncthreads();
#pragma unroll
        for (int k0 = 0; k0 < 128; k0 += 8) {
            uint32_t af[4][4], bf[4][2];
#pragma unroll
            for (int mt = 0; mt < 4; mt++) {
                const uint32_t* p = As + (mwo + mt * 16 + g) * 132 + k0 + tg;
                af[mt][0] = p[0]; af[mt][1] = p[8 * 132];
                af[mt][2] = p[4]; af[mt][3] = p[8 * 132 + 4];
            }
#pragma unroll
            for (int nt = 0; nt < 4; nt++) {
                const uint32_t* p = Ws + (nwo + nt * 8 + g) * 132 + k0 + tg;
                bf[nt][0] = p[0]; bf[nt][1] = p[4];
            }
#pragma unroll
            for (int mt = 0; mt < 4; mt++)
#pragma unroll
                for (int nt = 0; nt < 4; nt++)
                    mma_tf32(acc[mt][nt], af[mt], bf[nt]);
        }
        __syncthreads();
    }
#pragma unroll
    for (int mt = 0; mt < 4; mt++) {
        int r0 = m0 + mwo + mt * 16 + g;
#pragma unroll
        for (int nt = 0; nt < 4; nt++) {
            int col = n0 + nwo + nt * 8 + tg * 2;
            float2 bv = *(const float2*)(bias + col);
            float2 o0 = make_float2(acc[mt][nt][0] + bv.x, acc[mt][nt][1] + bv.y);
            float2 o1 = make_float2(acc[mt][nt][2] + bv.x, acc[mt][nt][3] + bv.y);
            *(float2*)(C + (size_t)r0 * Ntot + col) = o0;
            *(float2*)(C + (size_t)(r0 + 8) * Ntot + col) = o1;
        }
    }
}

// =====================================================================
// TC attention: logit[m] = sum_n tanh(A[m].W[:,n] + bias[n]) * proj[n]
// A [M][256], W [256(h)][256(n)] row-major. BM=128, N=256 full, BK=64.
// 256 thr, warps 2m x 4n, warp tile 64x64.
// =====================================================================
__global__ void __launch_bounds__(256) att_tc(
    const float* __restrict__ A, const float* __restrict__ W,
    const float* __restrict__ bias, const float* __restrict__ proj,
    float* __restrict__ logit)
{
    extern __shared__ uint32_t sma[];
    uint32_t* As = sma;                // [128][68]
    uint32_t* Ws = sma + 128 * 68;     // [64][264]  (k-major rows)
    const int tid = threadIdx.x, lane = tid & 31, w = tid >> 5;
    const int g = lane >> 2, tg = lane & 3;
    const int m0 = blockIdx.x * 128;
    const int mwo = (w >> 2) * 64, nwo = (w & 3) * 64;

    const int alr = tid >> 1, alh = (tid & 1) * 32;
    const int wlr = tid >> 2, wlh = (tid & 3) * 64;

    float acc[4][8][4];
#pragma unroll
    for (int a = 0; a < 4; a++)
#pragma unroll
        for (int b = 0; b < 8; b++)
#pragma unroll
            for (int c = 0; c < 4; c++) acc[a][b][c] = 0.f;

    for (int kc = 0; kc < 256; kc += 64) {
#pragma unroll
        for (int i = 0; i < 8; i++) {
            int col = alh + i * 4;
            float4 av = *(const float4*)(A + (size_t)(m0 + alr) * 256 + kc + col);
            uint32_t* ad = As + alr * 68 + col;
            ad[0] = f2tf(av.x); ad[1] = f2tf(av.y); ad[2] = f2tf(av.z); ad[3] = f2tf(av.w);
        }
#pragma unroll
        for (int i = 0; i < 16; i++) {
            int col = wlh + i * 4;
            float4 wv = *(const float4*)(W + (size_t)(kc + wlr) * 256 + col);
            uint32_t* wd = Ws + wlr * 264 + col;
            wd[0] = f2tf(wv.x); wd[1] = f2tf(wv.y); wd[2] = f2tf(wv.z); wd[3] = f2tf(wv.w);
        }
        __syncthreads();
#pragma unroll
        for (int k0 = 0; k0 < 64; k0 += 8) {
            uint32_t af[4][4], bf[8][2];
#pragma unroll
            for (int mt = 0; mt < 4; mt++) {
                const uint32_t* p = As + (mwo + mt * 16 + g) * 68 + k0 + tg;
                af[mt][0] = p[0]; af[mt][1] = p[8 * 68];
                af[mt][2] = p[4]; af[mt][3] = p[8 * 68 + 4];
            }
#pragma unroll
            for (int nt = 0; nt < 8; nt++) {
                const uint32_t* p = Ws + (k0 + tg) * 264 + nwo + nt * 8 + g;
                bf[nt][0] = p[0]; bf[nt][1] = p[4 * 264];
            }
#pragma unroll
            for (int mt = 0; mt < 4; mt++)
#pragma unroll
                for (int nt = 0; nt < 8; nt++)
                    mma_tf32(acc[mt][nt], af[mt], bf[nt]);
        }
        __syncthreads();
    }
    // epilogue: tanh(acc + bias)*proj, reduce over all 256 n
    float* red = (float*)sma;   // [128][4]
#pragma unroll
    for (int mt = 0; mt < 4; mt++) {
        float pa = 0.f, pb = 0.f;
#pragma unroll
        for (int nt = 0; nt < 8; nt++) {
            int col = nwo + nt * 8 + tg * 2;
            float2 bv = *(const float2*)(bias + col);
            float2 pv = *(const float2*)(proj + col);
            pa += tanh_clamped(acc[mt][nt][0] + bv.x) * pv.x
                + tanh_clamped(acc[mt][nt][1] + bv.y) * pv.y;
            pb += tanh_clamped(acc[mt][nt][2] + bv.x) * pv.x
                + tanh_clamped(acc[mt][nt][3] + bv.y) * pv.y;
        }
        pa += __shfl_xor_sync(0xffffffffu, pa, 1);
        pa += __shfl_xor_sync(0xffffffffu, pa, 2);
        pb += __shfl_xor_sync(0xffffffffu, pb, 1);
        pb += __shfl_xor_sync(0xffffffffu, pb, 2);
        if (tg == 0) {
            red[(mwo + mt * 16 + g) * 4 + (w & 3)] = pa;
            red[(mwo + mt * 16 + g + 8) * 4 + (w & 3)] = pb;
        }
    }
    __syncthreads();
    if (tid < 128) {
        float s = red[tid * 4] + red[tid * 4 + 1] + red[tid * 4 + 2] + red[tid * 4 + 3];
        logit[m0 + tid] = s;
    }
}

// =====================================================================
// GRU recurrence (unchanged from R2, fp32 SIMT).
// =====================================================================
__global__ void __launch_bounds__(256) gru_rec(
    const float* __restrict__ xg, float* __restrict__ out,
    const float* __restrict__ Whh, const float* __restrict__ bhh,
    int nsteps, size_t chain_xg, size_t chain_out)
{
    extern __shared__ float sm[];
    float* Wt = sm;               // [128][384]
    float* ht = sm + 128 * 384;   // [128][32] swizzled
    const int tid = threadIdx.x, lane = tid & 31, warp = tid >> 5;
    const int dir = blockIdx.y, chain = blockIdx.z;
    const int bCTA = blockIdx.x * 32;
    const int bl = warp * 4;
    const int j0 = lane * 4;
    const int swz_self = (lane & 7) << 2;

    const float* wsrc = Whh + (size_t)dir * 384 * 128;
    for (int idx = tid; idx < 384 * 32; idx += 256) {
        int g = idx >> 5, kk = (idx & 31) << 2;
        float4 v = *(const float4*)(wsrc + g * 128 + kk);
        Wt[(kk + 0) * 384 + g] = v.x; Wt[(kk + 1) * 384 + g] = v.y;
        Wt[(kk + 2) * 384 + g] = v.z; Wt[(kk + 3) * 384 + g] = v.w;
    }
    for (int idx = tid; idx < 128 * 32; idx += 256) ht[idx] = 0.f;

    float bh[3][4];
#pragma unroll
    for (int g = 0; g < 3; g++) {
        float4 v = *(const float4*)(bhh + dir * 384 + g * 128 + j0);
        bh[g][0] = v.x; bh[g][1] = v.y; bh[g][2] = v.z; bh[g][3] = v.w;
    }
    const float* xbase = xg + chain * chain_xg + dir * 384;
    float* obase = out + chain * chain_out + dir * 128;
    __syncthreads();

    for (int stp = 0; stp < nsteps; stp++) {
        const int t = dir ? (nsteps - 1 - stp) : stp;
        float xv[3][4][4];
#pragma unroll
        for (int bb = 0; bb < 4; bb++) {
            const float* row = xbase + ((size_t)t * 64 + bCTA + bl + bb) * 768;
#pragma unroll
            for (int g = 0; g < 3; g++) {
                float4 v = *(const float4*)(row + g * 128 + j0);
                xv[g][bb][0] = v.x; xv[g][bb][1] = v.y; xv[g][bb][2] = v.z; xv[g][bb][3] = v.w;
            }
        }
        float acc[3][4][4];
#pragma unroll
        for (int g = 0; g < 3; g++)
#pragma unroll
            for (int bb = 0; bb < 4; bb++)
#pragma unroll
                for (int jj = 0; jj < 4; jj++) acc[g][bb][jj] = bh[g][jj];

#pragma unroll 4
        for (int k = 0; k < 128; k++) {
            int sw = ((k >> 2) & 7) << 2;
            float4 hv = *(const float4*)&ht[k * 32 + (bl ^ sw)];
            const float* wk = Wt + k * 384 + j0;
            float4 wr = *(const float4*)(wk);
            float4 wz = *(const float4*)(wk + 128);
            float4 wn = *(const float4*)(wk + 256);
            float hb[4] = {hv.x, hv.y, hv.z, hv.w};
            float r4[4] = {wr.x, wr.y, wr.z, wr.w};
            float z4[4] = {wz.x, wz.y, wz.z, wz.w};
            float n4[4] = {wn.x, wn.y, wn.z, wn.w};
#pragma unroll
            for (int bb = 0; bb < 4; bb++)
#pragma unroll
                for (int jj = 0; jj < 4; jj++) {
                    acc[0][bb][jj] += hb[bb] * r4[jj];
                    acc[1][bb][jj] += hb[bb] * z4[jj];
                    acc[2][bb][jj] += hb[bb] * n4[jj];
                }
        }
        float hold[4][4];
#pragma unroll
        for (int bb = 0; bb < 4; bb++)
#pragma unroll
            for (int jj = 0; jj < 4; jj++)
                hold[bb][jj] = ht[(j0 + jj) * 32 + ((bl + bb) ^ swz_self)];
        __syncthreads();

#pragma unroll
        for (int bb = 0; bb < 4; bb++) {
            float4 o;
            float* op = (float*)&o;
#pragma unroll
            for (int jj = 0; jj < 4; jj++) {
                float r = sigf(xv[0][bb][jj] + acc[0][bb][jj]);
                float z = sigf(xv[1][bb][jj] + acc[1][bb][jj]);
                float n = tanh_clamped(xv[2][bb][jj] + r * acc[2][bb][jj]);
                float h = (1.f - z) * n + z * hold[bb][jj];
                ht[(j0 + jj) * 32 + ((bl + bb) ^ swz_self)] = h;
                op[jj] = h;
            }
            *(float4*)(obase + ((size_t)t * 64 + bCTA + bl + bb) * 256 + j0) = o;
        }
        __syncthreads();
    }
}

// ===================== softmax over T + weighted sum =================
__global__ void __launch_bounds__(256) softk(
    const float* __restrict__ logit, const float* __restrict__ out1,
    float* __restrict__ sent)
{
    const int s = blockIdx.x, b = blockIdx.y, tid = threadIdx.x;
    __shared__ float w[64];
    if (tid < 64) w[tid] = logit[(s * 64 + tid) * 64 + b];
    __syncthreads();
    if (tid < 32) {
        float a0 = w[tid], a1 = w[tid + 32];
        float mx = fmaxf(a0, a1);
#pragma unroll
        for (int off = 16; off > 0; off >>= 1)
            mx = fmaxf(mx, __shfl_xor_sync(0xffffffffu, mx, off));
        float e0 = __expf(a0 - mx), e1 = __expf(a1 - mx);
        float sum = e0 + e1;
#pragma unroll
        for (int off = 16; off > 0; off >>= 1)
            sum += __shfl_xor_sync(0xffffffffu, sum, off);
        float inv = 1.f / sum;
        w[tid] = e0 * inv; w[tid + 32] = e1 * inv;
    }
    __syncthreads();
    float acc = 0.f;
    const float* base = out1 + ((size_t)s * 64 * 64 + b) * 256 + tid;
#pragma unroll 8
    for (int t = 0; t < 64; t++)
        acc += w[t] * base[(size_t)t * 64 * 256];
    sent[(size_t)(s * 64 + b) * 256 + tid] = acc;
}

// ===================== final: doc vec + linear =======================
__global__ void __launch_bounds__(256) finalk(
    const float* __restrict__ out2, const float* __restrict__ a2,
    const float* __restrict__ Wf, const float* __restrict__ bf,
    float* __restrict__ out)
{
    const int b = blockIdx.x, tid = threadIdx.x;
    __shared__ float doc[256];
    float acc = 0.f;
#pragma unroll 8
    for (int s = 0; s < 32; s++)
        acc += a2[s * 64 + b] * out2[(size_t)(s * 64 + b) * 256 + tid];
    doc[tid] = acc;
    __syncthreads();
    if (tid < 5) {
        float r = bf[tid];
        for (int h = 0; h < 256; h++) r += doc[h] * Wf[tid * 256 + h];
        out[b * 5 + tid] = r;
    }
}

// =====================================================================
extern "C" void kernel_launch(void* const* d_in, const int* in_sizes, int n_in,
                              void* d_out, int out_size)
{
    (void)in_sizes; (void)n_in; (void)out_size;
    const int*   tokens = (const int*)  d_in[0];
    const float* embed  = (const float*)d_in[1];
    const float* Wih_a  = (const float*)d_in[2];
    const float* Whh_a  = (const float*)d_in[3];
    const float* bih_a  = (const float*)d_in[4];
    const float* bhh_a  = (const float*)d_in[5];
    const float* WW_a   = (const float*)d_in[6];
    const float* b_a    = (const float*)d_in[7];
    const float* proj_a = (const float*)d_in[8];
    const float* Wih_b  = (const float*)d_in[9];
    const float* Whh_b  = (const float*)d_in[10];
    const float* bih_b  = (const float*)d_in[11];
    const float* bhh_b  = (const float*)d_in[12];
    const float* WW_b   = (const float*)d_in[13];
    const float* b_b    = (const float*)d_in[14];
    const float* proj_b = (const float*)d_in[15];
    const float* Wf     = (const float*)d_in[16];
    const float* bf     = (const float*)d_in[17];
    float* out = (float*)d_out;

    float *xg, *out1, *logit, *sent, *xg2, *out2, *a2;
    cudaGetSymbolAddress((void**)&xg,    g_xg);
    cudaGetSymbolAddress((void**)&out1,  g_out1);
    cudaGetSymbolAddress((void**)&logit, g_logit);
    cudaGetSymbolAddress((void**)&sent,  g_sent);
    cudaGetSymbolAddress((void**)&xg2,   g_xg2);
    cudaGetSymbolAddress((void**)&out2,  g_out2);
    cudaGetSymbolAddress((void**)&a2,    g_a2);

    const int rec_smem  = (128 * 384 + 128 * 32) * (int)sizeof(float);   // 212992
    const int gemm_smem = 2 * 128 * 132 * (int)sizeof(uint32_t);         // 135168
    const int att_smem  = (128 * 68 + 64 * 264) * (int)sizeof(uint32_t); // 102400
    cudaFuncSetAttribute(gru_rec,       cudaFuncAttributeMaxDynamicSharedMemorySize, rec_smem);
    cudaFuncSetAttribute(gemm_tc<true>, cudaFuncAttributeMaxDynamicSharedMemorySize, gemm_smem);
    cudaFuncSetAttribute(gemm_tc<false>,cudaFuncAttributeMaxDynamicSharedMemorySize, gemm_smem);
    cudaFuncSetAttribute(att_tc,        cudaFuncAttributeMaxDynamicSharedMemorySize, att_smem);

    // 1) intra input gates: [131072,768] = gather(emb) @ Wih_intra^T + bih
    gemm_tc<true><<<dim3(6, 1024), 256, gemm_smem>>>(embed, tokens, Wih_a, bih_a, xg, 768, 128);
    // 2) intra biGRU
    gru_rec<<<dim3(2, 2, 32), 256, rec_smem>>>(
        xg, out1, Whh_a, bhh_a, 64, (size_t)64 * 64 * 768, (size_t)64 * 64 * 256);
    // 3) token attention logits
    att_tc<<<1024, 256, att_smem>>>(out1, WW_a, b_a, proj_a, logit);
    // 4) softmax over tokens + weighted sum
    softk<<<dim3(32, 64), 256>>>(logit, out1, sent);
    // 5) inter input gates: [2048,768] = sent @ Wih_inter^T + bih
    gemm_tc<false><<<dim3(6, 16), 256, gemm_smem>>>(sent, nullptr, Wih_b, bih_b, xg2, 768, 256);
    // 6) inter biGRU
    gru_rec<<<dim3(2, 2, 1), 256, rec_smem>>>(xg2, out2, Whh_b, bhh_b, 32, 0, 0);
    // 7) sentence attention scores (no softmax)
    att_tc<<<16, 256, att_smem>>>(out2, WW_b, b_b, proj_b, a2);
    // 8) doc vector + final linear
    finalk<<<64, 256>>>(out2, a2, Wf, bf, out);
}

// round 5
// speedup vs baseline: 1.7520x; 1.3747x over previous
#include <cuda_runtime.h>
#include <cuda_bf16.h>
#include <cstddef>
#include <cstdint>

// S=32, T=64, B=64, E=H=G=128, C=5
#define M1 131072
#define M2 2048

__device__ float g_xg  [100663296];  // [M1][768]
__device__ float g_out1[33554432];   // [M1][256]
__device__ float g_logit[131072];
__device__ float g_sent[524288];     // [M2][256]
__device__ float g_xg2 [1572864];    // [M2][768]
__device__ float g_out2[524288];     // [M2][256]
__device__ float g_a2  [2048];

__device__ __forceinline__ float sigf(float x) { return 1.f / (1.f + __expf(-x)); }
__device__ __forceinline__ float tanh_clamped(float x) {
    float a = fminf(fmaxf(x, -15.f), 15.f);
    float e = __expf(-2.f * a);
    return (1.f - e) / (1.f + e);
}
__device__ __forceinline__ uint32_t f2tf(float x) {
    uint32_t r; asm("cvt.rna.tf32.f32 %0, %1;" : "=r"(r) : "f"(x)); return r;
}
__device__ __forceinline__ void mma_tf32(float* d, const uint32_t* a, const uint32_t* b) {
    asm volatile(
        "mma.sync.aligned.m16n8k8.row.col.f32.tf32.tf32.f32 "
        "{%0,%1,%2,%3}, {%4,%5,%6,%7}, {%8,%9}, {%0,%1,%2,%3};\n"
        : "+f"(d[0]), "+f"(d[1]), "+f"(d[2]), "+f"(d[3])
        : "r"(a[0]), "r"(a[1]), "r"(a[2]), "r"(a[3]), "r"(b[0]), "r"(b[1]));
}
__device__ __forceinline__ void mma_bf16(float* d, const uint32_t* a, uint32_t b0, uint32_t b1) {
    asm volatile(
        "mma.sync.aligned.m16n8k16.row.col.f32.bf16.bf16.f32 "
        "{%0,%1,%2,%3}, {%4,%5,%6,%7}, {%8,%9}, {%0,%1,%2,%3};\n"
        : "+f"(d[0]), "+f"(d[1]), "+f"(d[2]), "+f"(d[3])
        : "r"(a[0]), "r"(a[1]), "r"(a[2]), "r"(a[3]), "r"(b0), "r"(b1));
}
__device__ __forceinline__ void ldsm4(uint32_t* r, uint32_t addr) {
    asm volatile("ldmatrix.sync.aligned.m8n8.x4.shared.b16 {%0,%1,%2,%3}, [%4];"
        : "=r"(r[0]), "=r"(r[1]), "=r"(r[2]), "=r"(r[3]) : "r"(addr));
}
// split (a,b) into bf16 hi pair + bf16 residual pair
__device__ __forceinline__ void bsplit(float a, float b, uint32_t& hi, uint32_t& lo) {
    __nv_bfloat16 ah = __float2bfloat16(a);
    __nv_bfloat16 bh = __float2bfloat16(b);
    __nv_bfloat16 al = __float2bfloat16(a - __bfloat162float(ah));
    __nv_bfloat16 bl = __float2bfloat16(b - __bfloat162float(bh));
    hi = ((uint32_t)__bfloat16_as_ushort(bh) << 16) | (uint32_t)__bfloat16_as_ushort(ah);
    lo = ((uint32_t)__bfloat16_as_ushort(bl) << 16) | (uint32_t)__bfloat16_as_ushort(al);
}

// =====================================================================
// TC GEMM (unchanged from R4)
// =====================================================================
template<bool GATHER>
__global__ void __launch_bounds__(256) gemm_tc(
    const float* __restrict__ A, const int* __restrict__ tokens,
    const float* __restrict__ W, const float* __restrict__ bias,
    float* __restrict__ C, int Ntot, int K)
{
    extern __shared__ uint32_t smg[];
    uint32_t* As = smg;                 // [128][132]
    uint32_t* Ws = smg + 128 * 132;     // [128][132]
    const int tid = threadIdx.x, lane = tid & 31, w = tid >> 5;
    const int g = lane >> 2, tg = lane & 3;
    const int m0 = blockIdx.y * 128, n0 = blockIdx.x * 128;
    const int mwo = (w >> 2) * 64, nwo = (w & 3) * 32;

    const int lr = tid >> 1, lh = (tid & 1) * 64;
    size_t arow;
    if (GATHER) arow = (size_t)tokens[m0 + lr] * K;
    else        arow = (size_t)(m0 + lr) * K;
    const size_t wrow = (size_t)(n0 + lr) * K;

    float acc[4][4][4];
#pragma unroll
    for (int a = 0; a < 4; a++)
#pragma unroll
        for (int b = 0; b < 4; b++)
#pragma unroll
            for (int c = 0; c < 4; c++) acc[a][b][c] = 0.f;

    for (int kc = 0; kc < K; kc += 128) {
#pragma unroll
        for (int i = 0; i < 16; i++) {
            int col = lh + i * 4;
            float4 av = *(const float4*)(A + arow + kc + col);
            float4 wv = *(const float4*)(W + wrow + kc + col);
            uint32_t* ad = As + lr * 132 + col;
            uint32_t* wd = Ws + lr * 132 + col;
            ad[0] = f2tf(av.x); ad[1] = f2tf(av.y); ad[2] = f2tf(av.z); ad[3] = f2tf(av.w);
            wd[0] = f2tf(wv.x); wd[1] = f2tf(wv.y); wd[2] = f2tf(wv.z); wd[3] = f2tf(wv.w);
        }
        __syncthreads();
#pragma unroll
        for (int k0 = 0; k0 < 128; k0 += 8) {
            uint32_t af[4][4], bf[4][2];
#pragma unroll
            for (int mt = 0; mt < 4; mt++) {
                const uint32_t* p = As + (mwo + mt * 16 + g) * 132 + k0 + tg;
                af[mt][0] = p[0]; af[mt][1] = p[8 * 132];
                af[mt][2] = p[4]; af[mt][3] = p[8 * 132 + 4];
            }
#pragma unroll
            for (int nt = 0; nt < 4; nt++) {
                const uint32_t* p = Ws + (nwo + nt * 8 + g) * 132 + k0 + tg;
                bf[nt][0] = p[0]; bf[nt][1] = p[4];
            }
#pragma unroll
            for (int mt = 0; mt < 4; mt++)
#pragma unroll
                for (int nt = 0; nt < 4; nt++)
                    mma_tf32(acc[mt][nt], af[mt], bf[nt]);
        }
        __syncthreads();
    }
#pragma unroll
    for (int mt = 0; mt < 4; mt++) {
        int r0 = m0 + mwo + mt * 16 + g;
#pragma unroll
        for (int nt = 0; nt < 4; nt++) {
            int col = n0 + nwo + nt * 8 + tg * 2;
            float2 bv = *(const float2*)(bias + col);
            float2 o0 = make_float2(acc[mt][nt][0] + bv.x, acc[mt][nt][1] + bv.y);
            float2 o1 = make_float2(acc[mt][nt][2] + bv.x, acc[mt][nt][3] + bv.y);
            *(float2*)(C + (size_t)r0 * Ntot + col) = o0;
            *(float2*)(C + (size_t)(r0 + 8) * Ntot + col) = o1;
        }
    }
}

// =====================================================================
// TC attention (unchanged from R4)
// =====================================================================
__global__ void __launch_bounds__(256) att_tc(
    const float* __restrict__ A, const float* __restrict__ W,
    const float* __restrict__ bias, const float* __restrict__ proj,
    float* __restrict__ logit)
{
    extern __shared__ uint32_t sma[];
    uint32_t* As = sma;                // [128][68]
    uint32_t* Ws = sma + 128 * 68;     // [64][264]
    const int tid = threadIdx.x, lane = tid & 31, w = tid >> 5;
    const int g = lane >> 2, tg = lane & 3;
    const int m0 = blockIdx.x * 128;
    const int mwo = (w >> 2) * 64, nwo = (w & 3) * 64;

    const int alr = tid >> 1, alh = (tid & 1) * 32;
    const int wlr = tid >> 2, wlh = (tid & 3) * 64;

    float acc[4][8][4];
#pragma unroll
    for (int a = 0; a < 4; a++)
#pragma unroll
        for (int b = 0; b < 8; b++)
#pragma unroll
            for (int c = 0; c < 4; c++) acc[a][b][c] = 0.f;

    for (int kc = 0; kc < 256; kc += 64) {
#pragma unroll
        for (int i = 0; i < 8; i++) {
            int col = alh + i * 4;
            float4 av = *(const float4*)(A + (size_t)(m0 + alr) * 256 + kc + col);
            uint32_t* ad = As + alr * 68 + col;
            ad[0] = f2tf(av.x); ad[1] = f2tf(av.y); ad[2] = f2tf(av.z); ad[3] = f2tf(av.w);
        }
#pragma unroll
        for (int i = 0; i < 16; i++) {
            int col = wlh + i * 4;
            float4 wv = *(const float4*)(W + (size_t)(kc + wlr) * 256 + col);
            uint32_t* wd = Ws + wlr * 264 + col;
            wd[0] = f2tf(wv.x); wd[1] = f2tf(wv.y); wd[2] = f2tf(wv.z); wd[3] = f2tf(wv.w);
        }
        __syncthreads();
#pragma unroll
        for (int k0 = 0; k0 < 64; k0 += 8) {
            uint32_t af[4][4], bf[8][2];
#pragma unroll
            for (int mt = 0; mt < 4; mt++) {
                const uint32_t* p = As + (mwo + mt * 16 + g) * 68 + k0 + tg;
                af[mt][0] = p[0]; af[mt][1] = p[8 * 68];
                af[mt][2] = p[4]; af[mt][3] = p[8 * 68 + 4];
            }
#pragma unroll
            for (int nt = 0; nt < 8; nt++) {
                const uint32_t* p = Ws + (k0 + tg) * 264 + nwo + nt * 8 + g;
                bf[nt][0] = p[0]; bf[nt][1] = p[4 * 264];
            }
#pragma unroll
            for (int mt = 0; mt < 4; mt++)
#pragma unroll
                for (int nt = 0; nt < 8; nt++)
                    mma_tf32(acc[mt][nt], af[mt], bf[nt]);
        }
        __syncthreads();
    }
    float* red = (float*)sma;
#pragma unroll
    for (int mt = 0; mt < 4; mt++) {
        float pa = 0.f, pb = 0.f;
#pragma unroll
        for (int nt = 0; nt < 8; nt++) {
            int col = nwo + nt * 8 + tg * 2;
            float2 bv = *(const float2*)(bias + col);
            float2 pv = *(const float2*)(proj + col);
            pa += tanh_clamped(acc[mt][nt][0] + bv.x) * pv.x
                + tanh_clamped(acc[mt][nt][1] + bv.y) * pv.y;
            pb += tanh_clamped(acc[mt][nt][2] + bv.x) * pv.x
                + tanh_clamped(acc[mt][nt][3] + bv.y) * pv.y;
        }
        pa += __shfl_xor_sync(0xffffffffu, pa, 1);
        pa += __shfl_xor_sync(0xffffffffu, pa, 2);
        pb += __shfl_xor_sync(0xffffffffu, pb, 1);
        pb += __shfl_xor_sync(0xffffffffu, pb, 2);
        if (tg == 0) {
            red[(mwo + mt * 16 + g) * 4 + (w & 3)] = pa;
            red[(mwo + mt * 16 + g + 8) * 4 + (w & 3)] = pb;
        }
    }
    __syncthreads();
    if (tid < 128) {
        float s = red[tid * 4] + red[tid * 4 + 1] + red[tid * 4 + 2] + red[tid * 4 + 3];
        logit[m0 + tid] = s;
    }
}

// =====================================================================
// Tensor-core GRU recurrence. One CTA = (chain, dir, 32-batch tile).
// M=32 (batch), N=384 (gates), K=128 (hidden). m16n8k16 bf16, 3-term
// hi/lo split (A_hi*B_hi + A_lo*B_hi + A_hi*B_lo) ~= fp32 precision.
// Warp w owns j-band [w*16,(w+1)*16): its 6 n-tiles are {j0,j0+8} in each
// of the r/z/n 128-col blocks, so r,z,n for one (b,j) land in ONE thread.
// h_prev lives in registers (full fp32); smem h (bf16 hi/lo pairs) only
// feeds next step's ldmatrix A-fragments.
// smem: Bsh 196608 B + h_hi 8704 + h_lo 8704 = 214016 B.
// =====================================================================
__global__ void __launch_bounds__(256) gru_rec_tc(
    const float* __restrict__ xg, float* __restrict__ out,
    const float* __restrict__ Whh, const float* __restrict__ bhh,
    int nsteps, size_t chain_xg, size_t chain_out)
{
    extern __shared__ uint32_t smr[];
    uint32_t* Bsh = smr;                 // [8w][8ks][6t][32 lanes] x uint4
    uint32_t* hhi = smr + 49152;         // [32][68] u32 (bf16x2)
    uint32_t* hlo = hhi + 32 * 68;       // [32][68]

    const int tid = threadIdx.x, lane = tid & 31, wrp = tid >> 5;
    const int g = lane >> 2, tg = lane & 3;
    const int dir = blockIdx.y, chain = blockIdx.z;
    const int bCTA = blockIdx.x * 32;

    // ---- build pre-shuffled, bf16-split B (Whh rows = gate cols) ----
    const float* wsrc = Whh + (size_t)dir * 384 * 128;
#pragma unroll 2
    for (int ks = 0; ks < 8; ks++)
#pragma unroll
        for (int tt = 0; tt < 6; tt++) {
            int n = (tt >> 1) * 128 + wrp * 16 + (tt & 1) * 8 + g;
            int k = ks * 16 + tg * 2;
            const float* p = wsrc + (size_t)n * 128 + k;
            uint32_t hi0, lo0, hi1, lo1;
            bsplit(p[0], p[1], hi0, lo0);
            bsplit(p[8], p[9], hi1, lo1);
            uint4* dst = (uint4*)Bsh + ((wrp * 8 + ks) * 6 + tt) * 32 + lane;
            *dst = make_uint4(hi0, hi1, lo0, lo1);
        }
    // zero h smem
    for (int idx = tid; idx < 32 * 68 * 2; idx += 256) hhi[idx] = 0.f ? 0u : 0u;
    for (int idx = tid; idx < 32 * 68; idx += 256) { hhi[idx] = 0u; hlo[idx] = 0u; }

    // bias per owned column pair, per tile
    float bn[6][2];
#pragma unroll
    for (int tt = 0; tt < 6; tt++) {
        int n0 = (tt >> 1) * 128 + wrp * 16 + (tt & 1) * 8 + tg * 2;
        float2 v = *(const float2*)(bhh + dir * 384 + n0);
        bn[tt][0] = v.x; bn[tt][1] = v.y;
    }
    // h_prev registers: [mt][p][c]  c: 0=(g,tg2) 1=(g,tg2+1) 2=(g+8,tg2) 3=(g+8,+1)
    float hreg[2][2][4];
#pragma unroll
    for (int a = 0; a < 2; a++)
#pragma unroll
        for (int b = 0; b < 2; b++)
#pragma unroll
            for (int c = 0; c < 4; c++) hreg[a][b][c] = 0.f;

    // ldmatrix base addresses (row = lane%16 within m-tile, colblock = lane/16)
    uint32_t hhi_sa = (uint32_t)__cvta_generic_to_shared(hhi);
    uint32_t hlo_sa = (uint32_t)__cvta_generic_to_shared(hlo);
    const uint32_t lmoff = (uint32_t)(((lane & 15) * 68 + (lane >> 4) * 4) * 4);

    const float* xbase = xg + chain * chain_xg + dir * 384;
    float* obase = out + chain * chain_out + dir * 128;
    __syncthreads();

    for (int stp = 0; stp < nsteps; stp++) {
        const int t = dir ? (nsteps - 1 - stp) : stp;
        // prefetch input gates for this thread's (b, gatecol) positions
        float2 xvv[2][6][2];
        const float* xrow = xbase + ((size_t)t * 64 + bCTA) * 768;
#pragma unroll
        for (int mt = 0; mt < 2; mt++)
#pragma unroll
            for (int tt = 0; tt < 6; tt++) {
                int n0 = (tt >> 1) * 128 + wrp * 16 + (tt & 1) * 8 + tg * 2;
                xvv[mt][tt][0] = *(const float2*)(xrow + (size_t)(mt * 16 + g) * 768 + n0);
                xvv[mt][tt][1] = *(const float2*)(xrow + (size_t)(mt * 16 + g + 8) * 768 + n0);
            }

        float acc[2][6][4];
#pragma unroll
        for (int mt = 0; mt < 2; mt++)
#pragma unroll
            for (int tt = 0; tt < 6; tt++) {
                acc[mt][tt][0] = bn[tt][0]; acc[mt][tt][1] = bn[tt][1];
                acc[mt][tt][2] = bn[tt][0]; acc[mt][tt][3] = bn[tt][1];
            }

#pragma unroll
        for (int ks = 0; ks < 8; ks++) {
            uint32_t ahi[2][4], alo[2][4];
#pragma unroll
            for (int mt = 0; mt < 2; mt++) {
                uint32_t off = lmoff + (uint32_t)(mt * 16 * 68 * 4 + ks * 32);
                ldsm4(ahi[mt], hhi_sa + off);
                ldsm4(alo[mt], hlo_sa + off);
            }
#pragma unroll
            for (int tt = 0; tt < 6; tt++) {
                uint4 bb = *((const uint4*)Bsh + ((wrp * 8 + ks) * 6 + tt) * 32 + lane);
#pragma unroll
                for (int mt = 0; mt < 2; mt++) {
                    mma_bf16(acc[mt][tt], ahi[mt], bb.x, bb.y);   // hi*hi
                    mma_bf16(acc[mt][tt], alo[mt], bb.x, bb.y);   // lo*hi
                    mma_bf16(acc[mt][tt], ahi[mt], bb.z, bb.w);   // hi*lo
                }
            }
        }
        // gate math (thread-local r,z,n), h_prev in regs
        float hnew[2][2][4];
#pragma unroll
        for (int mt = 0; mt < 2; mt++)
#pragma unroll
            for (int p = 0; p < 2; p++) {
                const float* xr = (const float*)xvv[mt][p];
                const float* xz = (const float*)xvv[mt][2 + p];
                const float* xn = (const float*)xvv[mt][4 + p];
#pragma unroll
                for (int c = 0; c < 4; c++) {
                    float rr = sigf(xr[c] + acc[mt][p][c]);
                    float zz = sigf(xz[c] + acc[mt][2 + p][c]);
                    float nn = tanh_clamped(xn[c] + rr * acc[mt][4 + p][c]);
                    float h  = (1.f - zz) * nn + zz * hreg[mt][p][c];
                    hreg[mt][p][c] = h;
                    hnew[mt][p][c] = h;
                }
            }
        __syncthreads();   // all ldmatrix reads of old h done
        // store new h (bf16 hi/lo pairs) + global out
        const int wcol = wrp * 8 + tg;   // word col base for p=0
#pragma unroll
        for (int mt = 0; mt < 2; mt++)
#pragma unroll
            for (int p = 0; p < 2; p++) {
                int col = wcol + p * 4;
                int r0 = mt * 16 + g, r1 = r0 + 8;
                uint32_t hi, lo;
                bsplit(hnew[mt][p][0], hnew[mt][p][1], hi, lo);
                hhi[r0 * 68 + col] = hi; hlo[r0 * 68 + col] = lo;
                bsplit(hnew[mt][p][2], hnew[mt][p][3], hi, lo);
                hhi[r1 * 68 + col] = hi; hlo[r1 * 68 + col] = lo;
                int j0 = wrp * 16 + p * 8 + tg * 2;
                *(float2*)(obase + ((size_t)t * 64 + bCTA + r0) * 256 + j0) =
                    make_float2(hnew[mt][p][0], hnew[mt][p][1]);
                *(float2*)(obase + ((size_t)t * 64 + bCTA + r1) * 256 + j0) =
                    make_float2(hnew[mt][p][2], hnew[mt][p][3]);
            }
        __syncthreads();   // new h visible before next step's ldmatrix
    }
}

// ===================== softmax over T + weighted sum =================
__global__ void __launch_bounds__(256) softk(
    const float* __restrict__ logit, const float* __restrict__ out1,
    float* __restrict__ sent)
{
    const int s = blockIdx.x, b = blockIdx.y, tid = threadIdx.x;
    __shared__ float w[64];
    if (tid < 64) w[tid] = logit[(s * 64 + tid) * 64 + b];
    __syncthreads();
    if (tid < 32) {
        float a0 = w[tid], a1 = w[tid + 32];
        float mx = fmaxf(a0, a1);
#pragma unroll
        for (int off = 16; off > 0; off >>= 1)
            mx = fmaxf(mx, __shfl_xor_sync(0xffffffffu, mx, off));
        float e0 = __expf(a0 - mx), e1 = __expf(a1 - mx);
        float sum = e0 + e1;
#pragma unroll
        for (int off = 16; off > 0; off >>= 1)
            sum += __shfl_xor_sync(0xffffffffu, sum, off);
        float inv = 1.f / sum;
        w[tid] = e0 * inv; w[tid + 32] = e1 * inv;
    }
    __syncthreads();
    float acc = 0.f;
    const float* base = out1 + ((size_t)s * 64 * 64 + b) * 256 + tid;
#pragma unroll 8
    for (int t = 0; t < 64; t++)
        acc += w[t] * base[(size_t)t * 64 * 256];
    sent[(size_t)(s * 64 + b) * 256 + tid] = acc;
}

// ===================== final: doc vec + linear =======================
__global__ void __launch_bounds__(256) finalk(
    const float* __restrict__ out2, const float* __restrict__ a2,
    const float* __restrict__ Wf, const float* __restrict__ bf,
    float* __restrict__ out)
{
    const int b = blockIdx.x, tid = threadIdx.x;
    __shared__ float doc[256];
    float acc = 0.f;
#pragma unroll 8
    for (int s = 0; s < 32; s++)
        acc += a2[s * 64 + b] * out2[(size_t)(s * 64 + b) * 256 + tid];
    doc[tid] = acc;
    __syncthreads();
    if (tid < 5) {
        float r = bf[tid];
        for (int h = 0; h < 256; h++) r += doc[h] * Wf[tid * 256 + h];
        out[b * 5 + tid] = r;
    }
}

// =====================================================================
extern "C" void kernel_launch(void* const* d_in, const int* in_sizes, int n_in,
                              void* d_out, int out_size)
{
    (void)in_sizes; (void)n_in; (void)out_size;
    const int*   tokens = (const int*)  d_in[0];
    const float* embed  = (const float*)d_in[1];
    const float* Wih_a  = (const float*)d_in[2];
    const float* Whh_a  = (const float*)d_in[3];
    const float* bih_a  = (const float*)d_in[4];
    const float* bhh_a  = (const float*)d_in[5];
    const float* WW_a   = (const float*)d_in[6];
    const float* b_a    = (const float*)d_in[7];
    const float* proj_a = (const float*)d_in[8];
    const float* Wih_b  = (const float*)d_in[9];
    const float* Whh_b  = (const float*)d_in[10];
    const float* bih_b  = (const float*)d_in[11];
    const float* bhh_b  = (const float*)d_in[12];
    const float* WW_b   = (const float*)d_in[13];
    const float* b_b    = (const float*)d_in[14];
    const float* proj_b = (const float*)d_in[15];
    const float* Wf     = (const float*)d_in[16];
    const float* bf     = (const float*)d_in[17];
    float* out = (float*)d_out;

    float *xg, *out1, *logit, *sent, *xg2, *out2, *a2;
    cudaGetSymbolAddress((void**)&xg,    g_xg);
    cudaGetSymbolAddress((void**)&out1,  g_out1);
    cudaGetSymbolAddress((void**)&logit, g_logit);
    cudaGetSymbolAddress((void**)&sent,  g_sent);
    cudaGetSymbolAddress((void**)&xg2,   g_xg2);
    cudaGetSymbolAddress((void**)&out2,  g_out2);
    cudaGetSymbolAddress((void**)&a2,    g_a2);

    const int gru_smem  = (49152 + 2 * 32 * 68) * (int)sizeof(uint32_t);  // 214016
    const int gemm_smem = 2 * 128 * 132 * (int)sizeof(uint32_t);          // 135168
    const int att_smem  = (128 * 68 + 64 * 264) * (int)sizeof(uint32_t);  // 102400
    cudaFuncSetAttribute(gru_rec_tc,    cudaFuncAttributeMaxDynamicSharedMemorySize, gru_smem);
    cudaFuncSetAttribute(gemm_tc<true>, cudaFuncAttributeMaxDynamicSharedMemorySize, gemm_smem);
    cudaFuncSetAttribute(gemm_tc<false>,cudaFuncAttributeMaxDynamicSharedMemorySize, gemm_smem);
    cudaFuncSetAttribute(att_tc,        cudaFuncAttributeMaxDynamicSharedMemorySize, att_smem);

    // 1) intra input gates
    gemm_tc<true><<<dim3(6, 1024), 256, gemm_smem>>>(embed, tokens, Wih_a, bih_a, xg, 768, 128);
    // 2) intra biGRU (tensor-core recurrence)
    gru_rec_tc<<<dim3(2, 2, 32), 256, gru_smem>>>(
        xg, out1, Whh_a, bhh_a, 64, (size_t)64 * 64 * 768, (size_t)64 * 64 * 256);
    // 3) token attention logits
    att_tc<<<1024, 256, att_smem>>>(out1, WW_a, b_a, proj_a, logit);
    // 4) softmax over tokens + weighted sum
    softk<<<dim3(32, 64), 256>>>(logit, out1, sent);
    // 5) inter input gates
    gemm_tc<false><<<dim3(6, 16), 256, gemm_smem>>>(sent, nullptr, Wih_b, bih_b, xg2, 768, 256);
    // 6) inter biGRU
    gru_rec_tc<<<dim3(2, 2, 1), 256, gru_smem>>>(xg2, out2, Whh_b, bhh_b, 32, 0, 0);
    // 7) sentence attention scores (no softmax)
    att_tc<<<16, 256, att_smem>>>(out2, WW_b, b_b, proj_b, a2);
    // 8) doc vector + final linear
    finalk<<<64, 256>>>(out2, a2, Wf, bf, out);
}

// round 7
// speedup vs baseline: 1.7917x; 1.0227x over previous
#include <cuda_runtime.h>
#include <cuda_bf16.h>
#include <cstddef>
#include <cstdint>

// S=32, T=64, B=64, E=H=G=128, C=5
#define M1 131072
#define M2 2048

__device__ float g_xg  [100663296];  // [M1][768]
__device__ float g_out1[33554432];   // [M1][256]
__device__ float g_logit[131072];
__device__ float g_sent[524288];     // [M2][256]
__device__ float g_xg2 [1572864];    // [M2][768]
__device__ float g_out2[524288];     // [M2][256]
__device__ float g_a2  [2048];
__device__ float g_wt  [131072];     // transposed W_W (intra 64K, inter 64K)

__device__ __forceinline__ float sigf(float x) { return 1.f / (1.f + __expf(-x)); }
__device__ __forceinline__ float tanh_clamped(float x) {
    float a = fminf(fmaxf(x, -15.f), 15.f);
    float e = __expf(-2.f * a);
    return (1.f - e) / (1.f + e);
}
__device__ __forceinline__ void mma_bf16(float* d, const uint32_t* a, uint32_t b0, uint32_t b1) {
    asm volatile(
        "mma.sync.aligned.m16n8k16.row.col.f32.bf16.bf16.f32 "
        "{%0,%1,%2,%3}, {%4,%5,%6,%7}, {%8,%9}, {%0,%1,%2,%3};\n"
        : "+f"(d[0]), "+f"(d[1]), "+f"(d[2]), "+f"(d[3])
        : "r"(a[0]), "r"(a[1]), "r"(a[2]), "r"(a[3]), "r"(b0), "r"(b1));
}
__device__ __forceinline__ void ldsm4(uint32_t* r, uint32_t addr) {
    asm volatile("ldmatrix.sync.aligned.m8n8.x4.shared.b16 {%0,%1,%2,%3}, [%4];"
        : "=r"(r[0]), "=r"(r[1]), "=r"(r[2]), "=r"(r[3]) : "r"(addr));
}
// split (a,b) into bf16 hi pair + bf16 residual pair
__device__ __forceinline__ void bsplit(float a, float b, uint32_t& hi, uint32_t& lo) {
    __nv_bfloat16 ah = __float2bfloat16(a);
    __nv_bfloat16 bh = __float2bfloat16(b);
    __nv_bfloat16 al = __float2bfloat16(a - __bfloat162float(ah));
    __nv_bfloat16 bl = __float2bfloat16(b - __bfloat162float(bh));
    hi = ((uint32_t)__bfloat16_as_ushort(bh) << 16) | (uint32_t)__bfloat16_as_ushort(ah);
    lo = ((uint32_t)__bfloat16_as_ushort(bl) << 16) | (uint32_t)__bfloat16_as_ushort(al);
}

// tiny transpose: out[n][h] = in[h][n], 256x256
__global__ void transp256(const float* __restrict__ in, float* __restrict__ out) {
    out[(size_t)threadIdx.x * 256 + blockIdx.x] = in[(size_t)blockIdx.x * 256 + threadIdx.x];
}

// =====================================================================
// bf16 3-term GEMM: C[m][n] = A'[m].W[n] + bias[n].
// A_hi*W_hi + A_lo*W_hi + A_hi*W_lo (~fp32 precision).
// A [M][K] K-contig (gathered if GATHER), W [N][K].
// Block 128x128, K-chunks of 128, 256 thr, warps 2m x 4n, warp 64x32.
// smem rows: 64 k-words + 4 pad (stride 68, conflict-free fragment LDS).
// =====================================================================
template<bool GATHER>
__global__ void __launch_bounds__(256) gemm_bf(
    const float* __restrict__ A, const int* __restrict__ tokens,
    const float* __restrict__ W, const float* __restrict__ bias,
    float* __restrict__ C, int Ntot, int K)
{
    extern __shared__ uint32_t smg[];
    uint32_t* Ahi = smg;                  // [128][68]
    uint32_t* Alo = smg + 128 * 68;
    uint32_t* Whi = smg + 2 * 128 * 68;
    uint32_t* Wlo = smg + 3 * 128 * 68;
    const int tid = threadIdx.x, lane = tid & 31, w = tid >> 5;
    const int g = lane >> 2, tg = lane & 3;
    const int m0 = blockIdx.y * 128, n0 = blockIdx.x * 128;
    const int mwo = (w >> 2) * 64, nwo = (w & 3) * 32;

    const int lr = tid >> 1;
    size_t arow;
    if (GATHER) arow = (size_t)tokens[m0 + lr] * K;
    else        arow = (size_t)(m0 + lr) * K;
    const size_t wrow = (size_t)(n0 + lr) * K;

    float acc[4][4][4];
#pragma unroll
    for (int a = 0; a < 4; a++)
#pragma unroll
        for (int b = 0; b < 4; b++)
#pragma unroll
            for (int c = 0; c < 4; c++) acc[a][b][c] = 0.f;

    for (int kc = 0; kc < K; kc += 128) {
#pragma unroll
        for (int i = 0; i < 16; i++) {
            int col = i * 8 + (tid & 1) * 4;           // 0..124 step 4
            float4 av = *(const float4*)(A + arow + kc + col);
            float4 wv = *(const float4*)(W + wrow + kc + col);
            int wd = col >> 1;
            uint32_t hi, lo;
            bsplit(av.x, av.y, hi, lo);
            Ahi[lr * 68 + wd] = hi; Alo[lr * 68 + wd] = lo;
            bsplit(av.z, av.w, hi, lo);
            Ahi[lr * 68 + wd + 1] = hi; Alo[lr * 68 + wd + 1] = lo;
            bsplit(wv.x, wv.y, hi, lo);
            Whi[lr * 68 + wd] = hi; Wlo[lr * 68 + wd] = lo;
            bsplit(wv.z, wv.w, hi, lo);
            Whi[lr * 68 + wd + 1] = hi; Wlo[lr * 68 + wd + 1] = lo;
        }
        __syncthreads();
#pragma unroll
        for (int kk = 0; kk < 8; kk++) {
            uint32_t ah[4][4], al[4][4];
#pragma unroll
            for (int mt = 0; mt < 4; mt++) {
                const uint32_t* p = Ahi + (mwo + mt * 16 + g) * 68 + kk * 8 + tg;
                ah[mt][0] = p[0]; ah[mt][1] = p[8 * 68];
                ah[mt][2] = p[4]; ah[mt][3] = p[8 * 68 + 4];
                const uint32_t* q = Alo + (mwo + mt * 16 + g) * 68 + kk * 8 + tg;
                al[mt][0] = q[0]; al[mt][1] = q[8 * 68];
                al[mt][2] = q[4]; al[mt][3] = q[8 * 68 + 4];
            }
#pragma unroll
            for (int nt = 0; nt < 4; nt++) {
                const uint32_t* qh = Whi + (nwo + nt * 8 + g) * 68 + kk * 8 + tg;
                uint32_t b0 = qh[0], b1 = qh[4];
                const uint32_t* ql = Wlo + (nwo + nt * 8 + g) * 68 + kk * 8 + tg;
                uint32_t c0 = ql[0], c1 = ql[4];
#pragma unroll
                for (int mt = 0; mt < 4; mt++) {
                    mma_bf16(acc[mt][nt], ah[mt], b0, b1);   // hi*hi
                    mma_bf16(acc[mt][nt], al[mt], b0, b1);   // lo*hi
                    mma_bf16(acc[mt][nt], ah[mt], c0, c1);   // hi*lo
                }
            }
        }
        __syncthreads();
    }
#pragma unroll
    for (int mt = 0; mt < 4; mt++) {
        int r0 = m0 + mwo + mt * 16 + g;
#pragma unroll
        for (int nt = 0; nt < 4; nt++) {
            int col = n0 + nwo + nt * 8 + tg * 2;
            float2 bv = *(const float2*)(bias + col);
            float2 o0 = make_float2(acc[mt][nt][0] + bv.x, acc[mt][nt][1] + bv.y);
            float2 o1 = make_float2(acc[mt][nt][2] + bv.x, acc[mt][nt][3] + bv.y);
            *(float2*)(C + (size_t)r0 * Ntot + col) = o0;
            *(float2*)(C + (size_t)(r0 + 8) * Ntot + col) = o1;
        }
    }
}

// =====================================================================
// bf16 3-term attention: logit[m]=sum_n tanh(A[m].Wt[n]+bias[n])*proj[n]
// A [M][256], Wt [256 n][256 k] (pre-transposed). BM=128, N=256 full,
// K-chunks 64. 256 thr, warps 2m x 4n, warp 64x64. smem stride 36.
// =====================================================================
__global__ void __launch_bounds__(256) att_bf(
    const float* __restrict__ A, const float* __restrict__ Wt,
    const float* __restrict__ bias, const float* __restrict__ proj,
    float* __restrict__ logit)
{
    extern __shared__ uint32_t sma[];
    uint32_t* Ahi = sma;                  // [128][36]
    uint32_t* Alo = sma + 128 * 36;
    uint32_t* Whi = sma + 2 * 128 * 36;   // [256][36]
    uint32_t* Wlo = sma + 2 * 128 * 36 + 256 * 36;
    const int tid = threadIdx.x, lane = tid & 31, w = tid >> 5;
    const int g = lane >> 2, tg = lane & 3;
    const int m0 = blockIdx.x * 128;
    const int mwo = (w >> 2) * 64, nwo = (w & 3) * 64;

    const int alr = tid >> 1;

    float acc[4][8][4];
#pragma unroll
    for (int a = 0; a < 4; a++)
#pragma unroll
        for (int b = 0; b < 8; b++)
#pragma unroll
            for (int c = 0; c < 4; c++) acc[a][b][c] = 0.f;

    for (int kc = 0; kc < 256; kc += 64) {
#pragma unroll
        for (int i = 0; i < 8; i++) {
            int col = i * 8 + (tid & 1) * 4;          // 0..60
            float4 av = *(const float4*)(A + (size_t)(m0 + alr) * 256 + kc + col);
            int wd = col >> 1;
            uint32_t hi, lo;
            bsplit(av.x, av.y, hi, lo);
            Ahi[alr * 36 + wd] = hi; Alo[alr * 36 + wd] = lo;
            bsplit(av.z, av.w, hi, lo);
            Ahi[alr * 36 + wd + 1] = hi; Alo[alr * 36 + wd + 1] = lo;
        }
#pragma unroll
        for (int i = 0; i < 16; i++) {
            int col = i * 4;
            float4 wv = *(const float4*)(Wt + (size_t)tid * 256 + kc + col);
            int wd = col >> 1;
            uint32_t hi, lo;
            bsplit(wv.x, wv.y, hi, lo);
            Whi[tid * 36 + wd] = hi; Wlo[tid * 36 + wd] = lo;
            bsplit(wv.z, wv.w, hi, lo);
            Whi[tid * 36 + wd + 1] = hi; Wlo[tid * 36 + wd + 1] = lo;
        }
        __syncthreads();
#pragma unroll
        for (int kk = 0; kk < 4; kk++) {
            uint32_t ah[4][4], al[4][4];
#pragma unroll
            for (int mt = 0; mt < 4; mt++) {
                const uint32_t* p = Ahi + (mwo + mt * 16 + g) * 36 + kk * 8 + tg;
                ah[mt][0] = p[0]; ah[mt][1] = p[8 * 36];
                ah[mt][2] = p[4]; ah[mt][3] = p[8 * 36 + 4];
                const uint32_t* q = Alo + (mwo + mt * 16 + g) * 36 + kk * 8 + tg;
                al[mt][0] = q[0]; al[mt][1] = q[8 * 36];
                al[mt][2] = q[4]; al[mt][3] = q[8 * 36 + 4];
            }
#pragma unroll
            for (int nt = 0; nt < 8; nt++) {
                const uint32_t* qh = Whi + (nwo + nt * 8 + g) * 36 + kk * 8 + tg;
                uint32_t b0 = qh[0], b1 = qh[4];
                const uint32_t* ql = Wlo + (nwo + nt * 8 + g) * 36 + kk * 8 + tg;
                uint32_t c0 = ql[0], c1 = ql[4];
#pragma unroll
                for (int mt = 0; mt < 4; mt++) {
                    mma_bf16(acc[mt][nt], ah[mt], b0, b1);
                    mma_bf16(acc[mt][nt], al[mt], b0, b1);
                    mma_bf16(acc[mt][nt], ah[mt], c0, c1);
                }
            }
        }
        __syncthreads();
    }
    // epilogue: tanh(acc + bias)*proj, reduce over all 256 n
    float* red = (float*)sma;   // [128][4]
#pragma unroll
    for (int mt = 0; mt < 4; mt++) {
        float pa = 0.f, pb = 0.f;
#pragma unroll
        for (int nt = 0; nt < 8; nt++) {
            int col = nwo + nt * 8 + tg * 2;
            float2 bv = *(const float2*)(bias + col);
            float2 pv = *(const float2*)(proj + col);
            pa += tanh_clamped(acc[mt][nt][0] + bv.x) * pv.x
                + tanh_clamped(acc[mt][nt][1] + bv.y) * pv.y;
            pb += tanh_clamped(acc[mt][nt][2] + bv.x) * pv.x
                + tanh_clamped(acc[mt][nt][3] + bv.y) * pv.y;
        }
        pa += __shfl_xor_sync(0xffffffffu, pa, 1);
        pa += __shfl_xor_sync(0xffffffffu, pa, 2);
        pb += __shfl_xor_sync(0xffffffffu, pb, 1);
        pb += __shfl_xor_sync(0xffffffffu, pb, 2);
        if (tg == 0) {
            red[(mwo + mt * 16 + g) * 4 + (w & 3)] = pa;
            red[(mwo + mt * 16 + g + 8) * 4 + (w & 3)] = pb;
        }
    }
    __syncthreads();
    if (tid < 128) {
        float s = red[tid * 4] + red[tid * 4 + 1] + red[tid * 4 + 2] + red[tid * 4 + 3];
        logit[m0 + tid] = s;
    }
}

// =====================================================================
// Tensor-core GRU recurrence (unchanged; 3-term bf16 split).
// =====================================================================
__global__ void __launch_bounds__(256) gru_rec_tc(
    const float* __restrict__ xg, float* __restrict__ out,
    const float* __restrict__ Whh, const float* __restrict__ bhh,
    int nsteps, size_t chain_xg, size_t chain_out)
{
    extern __shared__ uint32_t smr[];
    uint32_t* Bsh = smr;                 // [8w][8ks][6t][32 lanes] x uint4
    uint32_t* hhi = smr + 49152;         // [32][68]
    uint32_t* hlo = hhi + 32 * 68;       // [32][68]

    const int tid = threadIdx.x, lane = tid & 31, wrp = tid >> 5;
    const int g = lane >> 2, tg = lane & 3;
    const int dir = blockIdx.y, chain = blockIdx.z;
    const int bCTA = blockIdx.x * 32;

    const float* wsrc = Whh + (size_t)dir * 384 * 128;
#pragma unroll 2
    for (int ks = 0; ks < 8; ks++)
#pragma unroll
        for (int tt = 0; tt < 6; tt++) {
            int n = (tt >> 1) * 128 + wrp * 16 + (tt & 1) * 8 + g;
            int k = ks * 16 + tg * 2;
            const float* p = wsrc + (size_t)n * 128 + k;
            uint32_t hi0, lo0, hi1, lo1;
            bsplit(p[0], p[1], hi0, lo0);
            bsplit(p[8], p[9], hi1, lo1);
            uint4* dst = (uint4*)Bsh + ((wrp * 8 + ks) * 6 + tt) * 32 + lane;
            *dst = make_uint4(hi0, hi1, lo0, lo1);
        }
    for (int idx = tid; idx < 32 * 68; idx += 256) { hhi[idx] = 0u; hlo[idx] = 0u; }

    float bn[6][2];
#pragma unroll
    for (int tt = 0; tt < 6; tt++) {
        int n0 = (tt >> 1) * 128 + wrp * 16 + (tt & 1) * 8 + tg * 2;
        float2 v = *(const float2*)(bhh + dir * 384 + n0);
        bn[tt][0] = v.x; bn[tt][1] = v.y;
    }
    float hreg[2][2][4];
#pragma unroll
    for (int a = 0; a < 2; a++)
#pragma unroll
        for (int b = 0; b < 2; b++)
#pragma unroll
            for (int c = 0; c < 4; c++) hreg[a][b][c] = 0.f;

    uint32_t hhi_sa = (uint32_t)__cvta_generic_to_shared(hhi);
    uint32_t hlo_sa = (uint32_t)__cvta_generic_to_shared(hlo);
    const uint32_t lmoff = (uint32_t)(((lane & 15) * 68 + (lane >> 4) * 4) * 4);

    const float* xbase = xg + chain * chain_xg + dir * 384;
    float* obase = out + chain * chain_out + dir * 128;
    __syncthreads();

    for (int stp = 0; stp < nsteps; stp++) {
        const int t = dir ? (nsteps - 1 - stp) : stp;
        float2 xvv[2][6][2];
        const float* xrow = xbase + ((size_t)t * 64 + bCTA) * 768;
#pragma unroll
        for (int mt = 0; mt < 2; mt++)
#pragma unroll
            for (int tt = 0; tt < 6; tt++) {
                int n0 = (tt >> 1) * 128 + wrp * 16 + (tt & 1) * 8 + tg * 2;
                xvv[mt][tt][0] = *(const float2*)(xrow + (size_t)(mt * 16 + g) * 768 + n0);
                xvv[mt][tt][1] = *(const float2*)(xrow + (size_t)(mt * 16 + g + 8) * 768 + n0);
            }

        float acc[2][6][4];
#pragma unroll
        for (int mt = 0; mt < 2; mt++)
#pragma unroll
            for (int tt = 0; tt < 6; tt++) {
                acc[mt][tt][0] = bn[tt][0]; acc[mt][tt][1] = bn[tt][1];
                acc[mt][tt][2] = bn[tt][0]; acc[mt][tt][3] = bn[tt][1];
            }

#pragma unroll
        for (int ks = 0; ks < 8; ks++) {
            uint32_t ahi[2][4], alo[2][4];
#pragma unroll
            for (int mt = 0; mt < 2; mt++) {
                uint32_t off = lmoff + (uint32_t)(mt * 16 * 68 * 4 + ks * 32);
                ldsm4(ahi[mt], hhi_sa + off);
                ldsm4(alo[mt], hlo_sa + off);
            }
#pragma unroll
            for (int tt = 0; tt < 6; tt++) {
                uint4 bb = *((const uint4*)Bsh + ((wrp * 8 + ks) * 6 + tt) * 32 + lane);
#pragma unroll
                for (int mt = 0; mt < 2; mt++) {
                    mma_bf16(acc[mt][tt], ahi[mt], bb.x, bb.y);   // hi*hi
                    mma_bf16(acc[mt][tt], alo[mt], bb.x, bb.y);   // lo*hi
                    mma_bf16(acc[mt][tt], ahi[mt], bb.z, bb.w);   // hi*lo
                }
            }
        }
        float hnew[2][2][4];
#pragma unroll
        for (int mt = 0; mt < 2; mt++)
#pragma unroll
            for (int p = 0; p < 2; p++) {
                const float* xr = (const float*)xvv[mt][p];
                const float* xz = (const float*)xvv[mt][2 + p];
                const float* xn = (const float*)xvv[mt][4 + p];
#pragma unroll
                for (int c = 0; c < 4; c++) {
                    float rr = sigf(xr[c] + acc[mt][p][c]);
                    float zz = sigf(xz[c] + acc[mt][2 + p][c]);
                    float nn = tanh_clamped(xn[c] + rr * acc[mt][4 + p][c]);
                    float h  = (1.f - zz) * nn + zz * hreg[mt][p][c];
                    hreg[mt][p][c] = h;
                    hnew[mt][p][c] = h;
                }
            }
        __syncthreads();
        const int wcol = wrp * 8 + tg;
#pragma unroll
        for (int mt = 0; mt < 2; mt++)
#pragma unroll
            for (int p = 0; p < 2; p++) {
                int col = wcol + p * 4;
                int r0 = mt * 16 + g, r1 = r0 + 8;
                uint32_t hi, lo;
                bsplit(hnew[mt][p][0], hnew[mt][p][1], hi, lo);
                hhi[r0 * 68 + col] = hi; hlo[r0 * 68 + col] = lo;
                bsplit(hnew[mt][p][2], hnew[mt][p][3], hi, lo);
                hhi[r1 * 68 + col] = hi; hlo[r1 * 68 + col] = lo;
                int j0 = wrp * 16 + p * 8 + tg * 2;
                *(float2*)(obase + ((size_t)t * 64 + bCTA + r0) * 256 + j0) =
                    make_float2(hnew[mt][p][0], hnew[mt][p][1]);
                *(float2*)(obase + ((size_t)t * 64 + bCTA + r1) * 256 + j0) =
                    make_float2(hnew[mt][p][2], hnew[mt][p][3]);
            }
        __syncthreads();
    }
}

// ===================== softmax over T + weighted sum =================
__global__ void __launch_bounds__(256) softk(
    const float* __restrict__ logit, const float* __restrict__ out1,
    float* __restrict__ sent)
{
    const int s = blockIdx.x, b = blockIdx.y, tid = threadIdx.x;
    __shared__ float w[64];
    if (tid < 64) w[tid] = logit[(s * 64 + tid) * 64 + b];
    __syncthreads();
    if (tid < 32) {
        float a0 = w[tid], a1 = w[tid + 32];
        float mx = fmaxf(a0, a1);
#pragma unroll
        for (int off = 16; off > 0; off >>= 1)
            mx = fmaxf(mx, __shfl_xor_sync(0xffffffffu, mx, off));
        float e0 = __expf(a0 - mx), e1 = __expf(a1 - mx);
        float sum = e0 + e1;
#pragma unroll
        for (int off = 16; off > 0; off >>= 1)
            sum += __shfl_xor_sync(0xffffffffu, sum, off);
        float inv = 1.f / sum;
        w[tid] = e0 * inv; w[tid + 32] = e1 * inv;
    }
    __syncthreads();
    float acc = 0.f;
    const float* base = out1 + ((size_t)s * 64 * 64 + b) * 256 + tid;
#pragma unroll 8
    for (int t = 0; t < 64; t++)
        acc += w[t] * base[(size_t)t * 64 * 256];
    sent[(size_t)(s * 64 + b) * 256 + tid] = acc;
}

// ===================== final: doc vec + linear =======================
__global__ void __launch_bounds__(256) finalk(
    const float* __restrict__ out2, const float* __restrict__ a2,
    const float* __restrict__ Wf, const float* __restrict__ bf,
    float* __restrict__ out)
{
    const int b = blockIdx.x, tid = threadIdx.x;
    __shared__ float doc[256];
    float acc = 0.f;
#pragma unroll 8
    for (int s = 0; s < 32; s++)
        acc += a2[s * 64 + b] * out2[(size_t)(s * 64 + b) * 256 + tid];
    doc[tid] = acc;
    __syncthreads();
    if (tid < 5) {
        float r = bf[tid];
        for (int h = 0; h < 256; h++) r += doc[h] * Wf[tid * 256 + h];
        out[b * 5 + tid] = r;
    }
}

// =====================================================================
extern "C" void kernel_launch(void* const* d_in, const int* in_sizes, int n_in,
                              void* d_out, int out_size)
{
    (void)in_sizes; (void)n_in; (void)out_size;
    const int*   tokens = (const int*)  d_in[0];
    const float* embed  = (const float*)d_in[1];
    const float* Wih_a  = (const float*)d_in[2];
    const float* Whh_a  = (const float*)d_in[3];
    const float* bih_a  = (const float*)d_in[4];
    const float* bhh_a  = (const float*)d_in[5];
    const float* WW_a   = (const float*)d_in[6];
    const float* b_a    = (const float*)d_in[7];
    const float* proj_a = (const float*)d_in[8];
    const float* Wih_b  = (const float*)d_in[9];
    const float* Whh_b  = (const float*)d_in[10];
    const float* bih_b  = (const float*)d_in[11];
    const float* bhh_b  = (const float*)d_in[12];
    const float* WW_b   = (const float*)d_in[13];
    const float* b_b    = (const float*)d_in[14];
    const float* proj_b = (const float*)d_in[15];
    const float* Wf     = (const float*)d_in[16];
    const float* bf     = (const float*)d_in[17];
    float* out = (float*)d_out;

    float *xg, *out1, *logit, *sent, *xg2, *out2, *a2, *wt;
    cudaGetSymbolAddress((void**)&xg,    g_xg);
    cudaGetSymbolAddress((void**)&out1,  g_out1);
    cudaGetSymbolAddress((void**)&logit, g_logit);
    cudaGetSymbolAddress((void**)&sent,  g_sent);
    cudaGetSymbolAddress((void**)&xg2,   g_xg2);
    cudaGetSymbolAddress((void**)&out2,  g_out2);
    cudaGetSymbolAddress((void**)&a2,    g_a2);
    cudaGetSymbolAddress((void**)&wt,    g_wt);

    const int gru_smem  = (49152 + 2 * 32 * 68) * (int)sizeof(uint32_t);      // 214016
    const int gemm_smem = 4 * 128 * 68 * (int)sizeof(uint32_t);               // 139264
    const int att_smem  = (2 * 128 * 36 + 2 * 256 * 36) * (int)sizeof(uint32_t); // 110592
    cudaFuncSetAttribute(gru_rec_tc,    cudaFuncAttributeMaxDynamicSharedMemorySize, gru_smem);
    cudaFuncSetAttribute(gemm_bf<true>, cudaFuncAttributeMaxDynamicSharedMemorySize, gemm_smem);
    cudaFuncSetAttribute(gemm_bf<false>,cudaFuncAttributeMaxDynamicSharedMemorySize, gemm_smem);
    cudaFuncSetAttribute(att_bf,        cudaFuncAttributeMaxDynamicSharedMemorySize, att_smem);

    // 0) one-time transposes of the two attention weight matrices
    transp256<<<256, 256>>>(WW_a, wt);
    transp256<<<256, 256>>>(WW_b, wt + 65536);
    // 1) intra input gates: gather(emb) @ Wih_intra^T + bih
    gemm_bf<true><<<dim3(6, 1024), 256, gemm_smem>>>(embed, tokens, Wih_a, bih_a, xg, 768, 128);
    // 2) intra biGRU (tensor-core recurrence)
    gru_rec_tc<<<dim3(2, 2, 32), 256, gru_smem>>>(
        xg, out1, Whh_a, bhh_a, 64, (size_t)64 * 64 * 768, (size_t)64 * 64 * 256);
    // 3) token attention logits
    att_bf<<<1024, 256, att_smem>>>(out1, wt, b_a, proj_a, logit);
    // 4) softmax over tokens + weighted sum
    softk<<<dim3(32, 64), 256>>>(logit, out1, sent);
    // 5) inter input gates
    gemm_bf<false><<<dim3(6, 16), 256, gemm_smem>>>(sent, nullptr, Wih_b, bih_b, xg2, 768, 256);
    // 6) inter biGRU
    gru_rec_tc<<<dim3(2, 2, 1), 256, gru_smem>>>(xg2, out2, Whh_b, bhh_b, 32, 0, 0);
    // 7) sentence attention scores (no softmax)
    att_bf<<<16, 256, att_smem>>>(out2, wt + 65536, b_b, proj_b, a2);
    // 8) doc vector + final linear
    finalk<<<64, 256>>>(out2, a2, Wf, bf, out);
}

// round 9
// speedup vs baseline: 1.9784x; 1.1042x over previous
#include <cuda_runtime.h>
#include <cuda_bf16.h>
#include <cstddef>
#include <cstdint>

// S=32, T=64, B=64, E=H=G=128, C=5
#define M1 131072
#define M2 2048

__device__ float g_xg  [100663296];  // [M1][768]
__device__ float g_out1[33554432];   // [M1][256]
__device__ float g_logit[131072];
__device__ float g_sent[524288];     // [M2][256]
__device__ float g_xg2 [1572864];    // [M2][768]
__device__ float g_out2[524288];     // [M2][256]
__device__ float g_a2  [2048];
__device__ float g_wt  [131072];     // transposed W_W (intra 64K, inter 64K)

__device__ __forceinline__ float sigf(float x) { return 1.f / (1.f + __expf(-x)); }
__device__ __forceinline__ float tanh_clamped(float x) {
    float a = fminf(fmaxf(x, -15.f), 15.f);
    float e = __expf(-2.f * a);
    return (1.f - e) / (1.f + e);
}
__device__ __forceinline__ void mma_bf16(float* d, const uint32_t* a, uint32_t b0, uint32_t b1) {
    asm volatile(
        "mma.sync.aligned.m16n8k16.row.col.f32.bf16.bf16.f32 "
        "{%0,%1,%2,%3}, {%4,%5,%6,%7}, {%8,%9}, {%0,%1,%2,%3};\n"
        : "+f"(d[0]), "+f"(d[1]), "+f"(d[2]), "+f"(d[3])
        : "r"(a[0]), "r"(a[1]), "r"(a[2]), "r"(a[3]), "r"(b0), "r"(b1));
}
__device__ __forceinline__ void ldsm4(uint32_t* r, uint32_t addr) {
    asm volatile("ldmatrix.sync.aligned.m8n8.x4.shared.b16 {%0,%1,%2,%3}, [%4];"
        : "=r"(r[0]), "=r"(r[1]), "=r"(r[2]), "=r"(r[3]) : "r"(addr));
}
__device__ __forceinline__ void bsplit(float a, float b, uint32_t& hi, uint32_t& lo) {
    __nv_bfloat16 ah = __float2bfloat16(a);
    __nv_bfloat16 bh = __float2bfloat16(b);
    __nv_bfloat16 al = __float2bfloat16(a - __bfloat162float(ah));
    __nv_bfloat16 bl = __float2bfloat16(b - __bfloat162float(bh));
    hi = ((uint32_t)__bfloat16_as_ushort(bh) << 16) | (uint32_t)__bfloat16_as_ushort(ah);
    lo = ((uint32_t)__bfloat16_as_ushort(bl) << 16) | (uint32_t)__bfloat16_as_ushort(al);
}

// tiny transpose: out[n][h] = in[h][n], 256x256
__global__ void transp256(const float* __restrict__ in, float* __restrict__ out) {
    out[(size_t)threadIdx.x * 256 + blockIdx.x] = in[(size_t)blockIdx.x * 256 + threadIdx.x];
}

// =====================================================================
// bf16 3-term GEMM (validated R7): C = A'.W^T + bias
// =====================================================================
template<bool GATHER>
__global__ void __launch_bounds__(256) gemm_bf(
    const float* __restrict__ A, const int* __restrict__ tokens,
    const float* __restrict__ W, const float* __restrict__ bias,
    float* __restrict__ C, int Ntot, int K)
{
    extern __shared__ uint32_t smg[];
    uint32_t* Ahi = smg;                  // [128][68]
    uint32_t* Alo = smg + 128 * 68;
    uint32_t* Whi = smg + 2 * 128 * 68;
    uint32_t* Wlo = smg + 3 * 128 * 68;
    const int tid = threadIdx.x, lane = tid & 31, w = tid >> 5;
    const int g = lane >> 2, tg = lane & 3;
    const int m0 = blockIdx.y * 128, n0 = blockIdx.x * 128;
    const int mwo = (w >> 2) * 64, nwo = (w & 3) * 32;

    const int lr = tid >> 1;
    size_t arow;
    if (GATHER) arow = (size_t)tokens[m0 + lr] * K;
    else        arow = (size_t)(m0 + lr) * K;
    const size_t wrow = (size_t)(n0 + lr) * K;

    float acc[4][4][4];
#pragma unroll
    for (int a = 0; a < 4; a++)
#pragma unroll
        for (int b = 0; b < 4; b++)
#pragma unroll
            for (int c = 0; c < 4; c++) acc[a][b][c] = 0.f;

    for (int kc = 0; kc < K; kc += 128) {
#pragma unroll
        for (int i = 0; i < 16; i++) {
            int col = i * 8 + (tid & 1) * 4;
            float4 av = *(const float4*)(A + arow + kc + col);
            float4 wv = *(const float4*)(W + wrow + kc + col);
            int wd = col >> 1;
            uint32_t hi, lo;
            bsplit(av.x, av.y, hi, lo);
            Ahi[lr * 68 + wd] = hi; Alo[lr * 68 + wd] = lo;
            bsplit(av.z, av.w, hi, lo);
            Ahi[lr * 68 + wd + 1] = hi; Alo[lr * 68 + wd + 1] = lo;
            bsplit(wv.x, wv.y, hi, lo);
            Whi[lr * 68 + wd] = hi; Wlo[lr * 68 + wd] = lo;
            bsplit(wv.z, wv.w, hi, lo);
            Whi[lr * 68 + wd + 1] = hi; Wlo[lr * 68 + wd + 1] = lo;
        }
        __syncthreads();
#pragma unroll
        for (int kk = 0; kk < 8; kk++) {
            uint32_t ah[4][4], al[4][4];
#pragma unroll
            for (int mt = 0; mt < 4; mt++) {
                const uint32_t* p = Ahi + (mwo + mt * 16 + g) * 68 + kk * 8 + tg;
                ah[mt][0] = p[0]; ah[mt][1] = p[8 * 68];
                ah[mt][2] = p[4]; ah[mt][3] = p[8 * 68 + 4];
                const uint32_t* q = Alo + (mwo + mt * 16 + g) * 68 + kk * 8 + tg;
                al[mt][0] = q[0]; al[mt][1] = q[8 * 68];
                al[mt][2] = q[4]; al[mt][3] = q[8 * 68 + 4];
            }
#pragma unroll
            for (int nt = 0; nt < 4; nt++) {
                const uint32_t* qh = Whi + (nwo + nt * 8 + g) * 68 + kk * 8 + tg;
                uint32_t b0 = qh[0], b1 = qh[4];
                const uint32_t* ql = Wlo + (nwo + nt * 8 + g) * 68 + kk * 8 + tg;
                uint32_t c0 = ql[0], c1 = ql[4];
#pragma unroll
                for (int mt = 0; mt < 4; mt++) {
                    mma_bf16(acc[mt][nt], ah[mt], b0, b1);
                    mma_bf16(acc[mt][nt], al[mt], b0, b1);
                    mma_bf16(acc[mt][nt], ah[mt], c0, c1);
                }
            }
        }
        __syncthreads();
    }
#pragma unroll
    for (int mt = 0; mt < 4; mt++) {
        int r0 = m0 + mwo + mt * 16 + g;
#pragma unroll
        for (int nt = 0; nt < 4; nt++) {
            int col = n0 + nwo + nt * 8 + tg * 2;
            float2 bv = *(const float2*)(bias + col);
            float2 o0 = make_float2(acc[mt][nt][0] + bv.x, acc[mt][nt][1] + bv.y);
            float2 o1 = make_float2(acc[mt][nt][2] + bv.x, acc[mt][nt][3] + bv.y);
            *(float2*)(C + (size_t)r0 * Ntot + col) = o0;
            *(float2*)(C + (size_t)(r0 + 8) * Ntot + col) = o1;
        }
    }
}

// =====================================================================
// bf16 3-term attention (validated R7)
// =====================================================================
__global__ void __launch_bounds__(256) att_bf(
    const float* __restrict__ A, const float* __restrict__ Wt,
    const float* __restrict__ bias, const float* __restrict__ proj,
    float* __restrict__ logit)
{
    extern __shared__ uint32_t sma[];
    uint32_t* Ahi = sma;                  // [128][36]
    uint32_t* Alo = sma + 128 * 36;
    uint32_t* Whi = sma + 2 * 128 * 36;   // [256][36]
    uint32_t* Wlo = sma + 2 * 128 * 36 + 256 * 36;
    const int tid = threadIdx.x, lane = tid & 31, w = tid >> 5;
    const int g = lane >> 2, tg = lane & 3;
    const int m0 = blockIdx.x * 128;
    const int mwo = (w >> 2) * 64, nwo = (w & 3) * 64;

    const int alr = tid >> 1;

    float acc[4][8][4];
#pragma unroll
    for (int a = 0; a < 4; a++)
#pragma unroll
        for (int b = 0; b < 8; b++)
#pragma unroll
            for (int c = 0; c < 4; c++) acc[a][b][c] = 0.f;

    for (int kc = 0; kc < 256; kc += 64) {
#pragma unroll
        for (int i = 0; i < 8; i++) {
            int col = i * 8 + (tid & 1) * 4;
            float4 av = *(const float4*)(A + (size_t)(m0 + alr) * 256 + kc + col);
            int wd = col >> 1;
            uint32_t hi, lo;
            bsplit(av.x, av.y, hi, lo);
            Ahi[alr * 36 + wd] = hi; Alo[alr * 36 + wd] = lo;
            bsplit(av.z, av.w, hi, lo);
            Ahi[alr * 36 + wd + 1] = hi; Alo[alr * 36 + wd + 1] = lo;
        }
#pragma unroll
        for (int i = 0; i < 16; i++) {
            int col = i * 4;
            float4 wv = *(const float4*)(Wt + (size_t)tid * 256 + kc + col);
            int wd = col >> 1;
            uint32_t hi, lo;
            bsplit(wv.x, wv.y, hi, lo);
            Whi[tid * 36 + wd] = hi; Wlo[tid * 36 + wd] = lo;
            bsplit(wv.z, wv.w, hi, lo);
            Whi[tid * 36 + wd + 1] = hi; Wlo[tid * 36 + wd + 1] = lo;
        }
        __syncthreads();
#pragma unroll
        for (int kk = 0; kk < 4; kk++) {
            uint32_t ah[4][4], al[4][4];
#pragma unroll
            for (int mt = 0; mt < 4; mt++) {
                const uint32_t* p = Ahi + (mwo + mt * 16 + g) * 36 + kk * 8 + tg;
                ah[mt][0] = p[0]; ah[mt][1] = p[8 * 36];
                ah[mt][2] = p[4]; ah[mt][3] = p[8 * 36 + 4];
                const uint32_t* q = Alo + (mwo + mt * 16 + g) * 36 + kk * 8 + tg;
                al[mt][0] = q[0]; al[mt][1] = q[8 * 36];
                al[mt][2] = q[4]; al[mt][3] = q[8 * 36 + 4];
            }
#pragma unroll
            for (int nt = 0; nt < 8; nt++) {
                const uint32_t* qh = Whi + (nwo + nt * 8 + g) * 36 + kk * 8 + tg;
                uint32_t b0 = qh[0], b1 = qh[4];
                const uint32_t* ql = Wlo + (nwo + nt * 8 + g) * 36 + kk * 8 + tg;
                uint32_t c0 = ql[0], c1 = ql[4];
#pragma unroll
                for (int mt = 0; mt < 4; mt++) {
                    mma_bf16(acc[mt][nt], ah[mt], b0, b1);
                    mma_bf16(acc[mt][nt], al[mt], b0, b1);
                    mma_bf16(acc[mt][nt], ah[mt], c0, c1);
                }
            }
        }
        __syncthreads();
    }
    float* red = (float*)sma;
#pragma unroll
    for (int mt = 0; mt < 4; mt++) {
        float pa = 0.f, pb = 0.f;
#pragma unroll
        for (int nt = 0; nt < 8; nt++) {
            int col = nwo + nt * 8 + tg * 2;
            float2 bv = *(const float2*)(bias + col);
            float2 pv = *(const float2*)(proj + col);
            pa += tanh_clamped(acc[mt][nt][0] + bv.x) * pv.x
                + tanh_clamped(acc[mt][nt][1] + bv.y) * pv.y;
            pb += tanh_clamped(acc[mt][nt][2] + bv.x) * pv.x
                + tanh_clamped(acc[mt][nt][3] + bv.y) * pv.y;
        }
        pa += __shfl_xor_sync(0xffffffffu, pa, 1);
        pa += __shfl_xor_sync(0xffffffffu, pa, 2);
        pb += __shfl_xor_sync(0xffffffffu, pb, 1);
        pb += __shfl_xor_sync(0xffffffffu, pb, 2);
        if (tg == 0) {
            red[(mwo + mt * 16 + g) * 4 + (w & 3)] = pa;
            red[(mwo + mt * 16 + g + 8) * 4 + (w & 3)] = pb;
        }
    }
    __syncthreads();
    if (tid < 128) {
        float s = red[tid * 4] + red[tid * 4 + 1] + red[tid * 4 + 2] + red[tid * 4 + 3];
        logit[m0 + tid] = s;
    }
}

// =====================================================================
// TC GRU recurrence, 16-warp version (512 thr). Warp w owns j-band
// [w*8, w*8+8): 3 n-tiles = one 8-wide tile per gate (r,z,n) so gate
// math stays thread-local. Same 3-term bf16 split, same smem budget:
// Bsh [16w][8ks][3t][32]xuint4 (196608B) + h hi/lo [32][68] each.
// =====================================================================
__global__ void __launch_bounds__(512) gru_rec_tc(
    const float* __restrict__ xg, float* __restrict__ out,
    const float* __restrict__ Whh, const float* __restrict__ bhh,
    int nsteps, size_t chain_xg, size_t chain_out)
{
    extern __shared__ uint32_t smr[];
    uint32_t* Bsh = smr;                 // 49152 u32
    uint32_t* hhi = smr + 49152;         // [32][68]
    uint32_t* hlo = hhi + 32 * 68;       // [32][68]

    const int tid = threadIdx.x, lane = tid & 31, wrp = tid >> 5;  // 0..15
    const int g = lane >> 2, tg = lane & 3;
    const int dir = blockIdx.y, chain = blockIdx.z;
    const int bCTA = blockIdx.x * 32;

    // ---- pre-shuffled, bf16-split B: warp w loads its own 3 tiles ----
    const float* wsrc = Whh + (size_t)dir * 384 * 128;
#pragma unroll 2
    for (int ks = 0; ks < 8; ks++)
#pragma unroll
        for (int tt = 0; tt < 3; tt++) {
            int n = tt * 128 + wrp * 8 + g;
            int k = ks * 16 + tg * 2;
            const float* p = wsrc + (size_t)n * 128 + k;
            uint32_t hi0, lo0, hi1, lo1;
            bsplit(p[0], p[1], hi0, lo0);
            bsplit(p[8], p[9], hi1, lo1);
            uint4* dst = (uint4*)Bsh + ((wrp * 8 + ks) * 3 + tt) * 32 + lane;
            *dst = make_uint4(hi0, hi1, lo0, lo1);
        }
    for (int idx = tid; idx < 32 * 68; idx += 512) { hhi[idx] = 0u; hlo[idx] = 0u; }

    float bn[3][2];
#pragma unroll
    for (int tt = 0; tt < 3; tt++) {
        int n0 = tt * 128 + wrp * 8 + tg * 2;
        float2 v = *(const float2*)(bhh + dir * 384 + n0);
        bn[tt][0] = v.x; bn[tt][1] = v.y;
    }
    float hreg[2][4];
#pragma unroll
    for (int a = 0; a < 2; a++)
#pragma unroll
        for (int c = 0; c < 4; c++) hreg[a][c] = 0.f;

    uint32_t hhi_sa = (uint32_t)__cvta_generic_to_shared(hhi);
    uint32_t hlo_sa = (uint32_t)__cvta_generic_to_shared(hlo);
    const uint32_t lmoff = (uint32_t)(((lane & 15) * 68 + (lane >> 4) * 4) * 4);

    const float* xbase = xg + chain * chain_xg + dir * 384;
    float* obase = out + chain * chain_out + dir * 128;
    __syncthreads();

    for (int stp = 0; stp < nsteps; stp++) {
        const int t = dir ? (nsteps - 1 - stp) : stp;
        // prefetch input gates (consumed after MMA phase)
        float2 xvv[2][3][2];
        const float* xrow = xbase + ((size_t)t * 64 + bCTA) * 768;
#pragma unroll
        for (int mt = 0; mt < 2; mt++)
#pragma unroll
            for (int tt = 0; tt < 3; tt++) {
                int n0 = tt * 128 + wrp * 8 + tg * 2;
                xvv[mt][tt][0] = *(const float2*)(xrow + (size_t)(mt * 16 + g) * 768 + n0);
                xvv[mt][tt][1] = *(const float2*)(xrow + (size_t)(mt * 16 + g + 8) * 768 + n0);
            }

        float acc[2][3][4];
#pragma unroll
        for (int mt = 0; mt < 2; mt++)
#pragma unroll
            for (int tt = 0; tt < 3; tt++) {
                acc[mt][tt][0] = bn[tt][0]; acc[mt][tt][1] = bn[tt][1];
                acc[mt][tt][2] = bn[tt][0]; acc[mt][tt][3] = bn[tt][1];
            }

#pragma unroll
        for (int ks = 0; ks < 8; ks++) {
            uint32_t ahi[2][4], alo[2][4];
#pragma unroll
            for (int mt = 0; mt < 2; mt++) {
                uint32_t off = lmoff + (uint32_t)(mt * 16 * 68 * 4 + ks * 32);
                ldsm4(ahi[mt], hhi_sa + off);
                ldsm4(alo[mt], hlo_sa + off);
            }
#pragma unroll
            for (int tt = 0; tt < 3; tt++) {
                uint4 bb = *((const uint4*)Bsh + ((wrp * 8 + ks) * 3 + tt) * 32 + lane);
#pragma unroll
                for (int mt = 0; mt < 2; mt++) {
                    mma_bf16(acc[mt][tt], ahi[mt], bb.x, bb.y);   // hi*hi
                    mma_bf16(acc[mt][tt], alo[mt], bb.x, bb.y);   // lo*hi
                    mma_bf16(acc[mt][tt], ahi[mt], bb.z, bb.w);   // hi*lo
                }
            }
        }
        // gate math: r,z,n tiles for this warp's j-band, thread-local
        float hnew[2][4];
#pragma unroll
        for (int mt = 0; mt < 2; mt++) {
            const float* xr = (const float*)xvv[mt][0];
            const float* xz = (const float*)xvv[mt][1];
            const float* xn = (const float*)xvv[mt][2];
#pragma unroll
            for (int c = 0; c < 4; c++) {
                float rr = sigf(xr[c] + acc[mt][0][c]);
                float zz = sigf(xz[c] + acc[mt][1][c]);
                float nn = tanh_clamped(xn[c] + rr * acc[mt][2][c]);
                float h  = (1.f - zz) * nn + zz * hreg[mt][c];
                hreg[mt][c] = h;
                hnew[mt][c] = h;
            }
        }
        __syncthreads();   // all ldmatrix reads of old h done
        const int wcol = wrp * 4 + tg;   // word col (j pair) 0..63
#pragma unroll
        for (int mt = 0; mt < 2; mt++) {
            int r0 = mt * 16 + g, r1 = r0 + 8;
            uint32_t hi, lo;
            bsplit(hnew[mt][0], hnew[mt][1], hi, lo);
            hhi[r0 * 68 + wcol] = hi; hlo[r0 * 68 + wcol] = lo;
            bsplit(hnew[mt][2], hnew[mt][3], hi, lo);
            hhi[r1 * 68 + wcol] = hi; hlo[r1 * 68 + wcol] = lo;
            int j0 = wrp * 8 + tg * 2;
            *(float2*)(obase + ((size_t)t * 64 + bCTA + r0) * 256 + j0) =
                make_float2(hnew[mt][0], hnew[mt][1]);
            *(float2*)(obase + ((size_t)t * 64 + bCTA + r1) * 256 + j0) =
                make_float2(hnew[mt][2], hnew[mt][3]);
        }
        __syncthreads();   // new h visible before next step's ldmatrix
    }
}

// ===================== softmax over T + weighted sum =================
__global__ void __launch_bounds__(256) softk(
    const float* __restrict__ logit, const float* __restrict__ out1,
    float* __restrict__ sent)
{
    const int s = blockIdx.x, b = blockIdx.y, tid = threadIdx.x;
    __shared__ float w[64];
    if (tid < 64) w[tid] = logit[(s * 64 + tid) * 64 + b];
    __syncthreads();
    if (tid < 32) {
        float a0 = w[tid], a1 = w[tid + 32];
        float mx = fmaxf(a0, a1);
#pragma unroll
        for (int off = 16; off > 0; off >>= 1)
            mx = fmaxf(mx, __shfl_xor_sync(0xffffffffu, mx, off));
        float e0 = __expf(a0 - mx), e1 = __expf(a1 - mx);
        float sum = e0 + e1;
#pragma unroll
        for (int off = 16; off > 0; off >>= 1)
            sum += __shfl_xor_sync(0xffffffffu, sum, off);
        float inv = 1.f / sum;
        w[tid] = e0 * inv; w[tid + 32] = e1 * inv;
    }
    __syncthreads();
    float acc = 0.f;
    const float* base = out1 + ((size_t)s * 64 * 64 + b) * 256 + tid;
#pragma unroll 8
    for (int t = 0; t < 64; t++)
        acc += w[t] * base[(size_t)t * 64 * 256];
    sent[(size_t)(s * 64 + b) * 256 + tid] = acc;
}

// ===================== final: doc vec + linear =======================
__global__ void __launch_bounds__(256) finalk(
    const float* __restrict__ out2, const float* __restrict__ a2,
    const float* __restrict__ Wf, const float* __restrict__ bf,
    float* __restrict__ out)
{
    const int b = blockIdx.x, tid = threadIdx.x;
    __shared__ float doc[256];
    float acc = 0.f;
#pragma unroll 8
    for (int s = 0; s < 32; s++)
        acc += a2[s * 64 + b] * out2[(size_t)(s * 64 + b) * 256 + tid];
    doc[tid] = acc;
    __syncthreads();
    if (tid < 5) {
        float r = bf[tid];
        for (int h = 0; h < 256; h++) r += doc[h] * Wf[tid * 256 + h];
        out[b * 5 + tid] = r;
    }
}

// =====================================================================
extern "C" void kernel_launch(void* const* d_in, const int* in_sizes, int n_in,
                              void* d_out, int out_size)
{
    (void)in_sizes; (void)n_in; (void)out_size;
    const int*   tokens = (const int*)  d_in[0];
    const float* embed  = (const float*)d_in[1];
    const float* Wih_a  = (const float*)d_in[2];
    const float* Whh_a  = (const float*)d_in[3];
    const float* bih_a  = (const float*)d_in[4];
    const float* bhh_a  = (const float*)d_in[5];
    const float* WW_a   = (const float*)d_in[6];
    const float* b_a    = (const float*)d_in[7];
    const float* proj_a = (const float*)d_in[8];
    const float* Wih_b  = (const float*)d_in[9];
    const float* Whh_b  = (const float*)d_in[10];
    const float* bih_b  = (const float*)d_in[11];
    const float* bhh_b  = (const float*)d_in[12];
    const float* WW_b   = (const float*)d_in[13];
    const float* b_b    = (const float*)d_in[14];
    const float* proj_b = (const float*)d_in[15];
    const float* Wf     = (const float*)d_in[16];
    const float* bf     = (const float*)d_in[17];
    float* out = (float*)d_out;

    float *xg, *out1, *logit, *sent, *xg2, *out2, *a2, *wt;
    cudaGetSymbolAddress((void**)&xg,    g_xg);
    cudaGetSymbolAddress((void**)&out1,  g_out1);
    cudaGetSymbolAddress((void**)&logit, g_logit);
    cudaGetSymbolAddress((void**)&sent,  g_sent);
    cudaGetSymbolAddress((void**)&xg2,   g_xg2);
    cudaGetSymbolAddress((void**)&out2,  g_out2);
    cudaGetSymbolAddress((void**)&a2,    g_a2);
    cudaGetSymbolAddress((void**)&wt,    g_wt);

    const int gru_smem  = (49152 + 2 * 32 * 68) * (int)sizeof(uint32_t);      // 214016
    const int gemm_smem = 4 * 128 * 68 * (int)sizeof(uint32_t);               // 139264
    const int att_smem  = (2 * 128 * 36 + 2 * 256 * 36) * (int)sizeof(uint32_t); // 110592
    cudaFuncSetAttribute(gru_rec_tc,    cudaFuncAttributeMaxDynamicSharedMemorySize, gru_smem);
    cudaFuncSetAttribute(gemm_bf<true>, cudaFuncAttributeMaxDynamicSharedMemorySize, gemm_smem);
    cudaFuncSetAttribute(gemm_bf<false>,cudaFuncAttributeMaxDynamicSharedMemorySize, gemm_smem);
    cudaFuncSetAttribute(att_bf,        cudaFuncAttributeMaxDynamicSharedMemorySize, att_smem);

    // 0) one-time transposes of the two attention weight matrices
    transp256<<<256, 256>>>(WW_a, wt);
    transp256<<<256, 256>>>(WW_b, wt + 65536);
    // 1) intra input gates: gather(emb) @ Wih_intra^T + bih
    gemm_bf<true><<<dim3(6, 1024), 256, gemm_smem>>>(embed, tokens, Wih_a, bih_a, xg, 768, 128);
    // 2) intra biGRU (tensor-core recurrence, 16 warps)
    gru_rec_tc<<<dim3(2, 2, 32), 512, gru_smem>>>(
        xg, out1, Whh_a, bhh_a, 64, (size_t)64 * 64 * 768, (size_t)64 * 64 * 256);
    // 3) token attention logits
    att_bf<<<1024, 256, att_smem>>>(out1, wt, b_a, proj_a, logit);
    // 4) softmax over tokens + weighted sum
    softk<<<dim3(32, 64), 256>>>(logit, out1, sent);
    // 5) inter input gates
    gemm_bf<false><<<dim3(6, 16), 256, gemm_smem>>>(sent, nullptr, Wih_b, bih_b, xg2, 768, 256);
    // 6) inter biGRU
    gru_rec_tc<<<dim3(2, 2, 1), 512, gru_smem>>>(xg2, out2, Whh_b, bhh_b, 32, 0, 0);
    // 7) sentence attention scores (no softmax)
    att_bf<<<16, 256, att_smem>>>(out2, wt + 65536, b_b, proj_b, a2);
    // 8) doc vector + final linear
    finalk<<<64, 256>>>(out2, a2, Wf, bf, out);
}